// round 2
// baseline (speedup 1.0000x reference)
#include <cuda_runtime.h>

// Problem constants
#define Bn   128
#define Sn   512
#define Hn   1000
#define NHn  8
#define DKn  125
#define Mrows (Bn * Sn)        // 65536

// ---------------------------------------------------------------------------
// Scratch (device globals; allocation in kernel_launch is forbidden)
// ---------------------------------------------------------------------------
__device__ __align__(16) float g_qh[(size_t)Mrows * Hn];
__device__ __align__(16) float g_kh[(size_t)Mrows * Hn];
__device__ __align__(16) float g_vh[(size_t)Mrows * Hn];
__device__ __align__(16) float g_z [(size_t)Mrows * Hn];
__device__ __align__(16) float g_y [(size_t)Mrows * Hn];

// ---------------------------------------------------------------------------
// Packed f32x2 helpers (sm_100+): doubles FFMA throughput vs 3-reg FFMA
// ---------------------------------------------------------------------------
__device__ __forceinline__ unsigned long long pk2(float lo, float hi) {
    unsigned long long r;
    asm("mov.b64 %0, {%1, %2};" : "=l"(r) : "f"(lo), "f"(hi));
    return r;
}
__device__ __forceinline__ void fma2(unsigned long long &d,
                                     unsigned long long a,
                                     unsigned long long b) {
    asm("fma.rn.f32x2 %0, %1, %2, %0;" : "+l"(d) : "l"(a), "l"(b));
}
__device__ __forceinline__ void upk2(unsigned long long v, float &lo, float &hi) {
    asm("mov.b64 {%0, %1}, %2;" : "=f"(lo), "=f"(hi) : "l"(v));
}

// ---------------------------------------------------------------------------
// GEMM: out[M,1000] = X[M,1000] @ W[1000,1000]^T + bias
// 128x128 block tile, K-step 8, 256 threads, 8x8 per-thread (f32x2 packed)
// K = 1000 = 125 * 8 exactly (no K guard). N = 1000 needs a guard on last tile.
// ---------------------------------------------------------------------------
__global__ __launch_bounds__(256)
void gemm_xwT_kernel(const float* __restrict__ X,
                     const float* __restrict__ W,
                     const float* __restrict__ bias,
                     float* __restrict__ out)
{
    __shared__ __align__(16) float As[8][128];
    __shared__ __align__(16) float Bs[8][128];

    const int m0 = blockIdx.y * 128;
    const int n0 = blockIdx.x * 128;
    const int t  = threadIdx.x;
    const int tx = t & 15;          // 0..15
    const int ty = t >> 4;          // 0..15

    // loading indices: each thread loads one float4 of A and one of B per k-tile
    const int lrow = t >> 1;        // 0..127
    const int lk4  = (t & 1) * 4;   // 0 or 4

    const float* Xp = X + (size_t)(m0 + lrow) * Hn;
    const float* Wp = W + (size_t)(n0 + lrow) * Hn;
    const bool wvalid = (n0 + lrow) < Hn;

    unsigned long long acc[8][4];
    #pragma unroll
    for (int r = 0; r < 8; r++)
        #pragma unroll
        for (int c = 0; c < 4; c++) acc[r][c] = 0ull;

    for (int kt = 0; kt < Hn; kt += 8) {
        float4 av = *(const float4*)(Xp + kt + lk4);
        float4 bv = wvalid ? *(const float4*)(Wp + kt + lk4)
                           : make_float4(0.f, 0.f, 0.f, 0.f);
        __syncthreads();   // previous iteration's compute done reading smem
        As[lk4 + 0][lrow] = av.x;
        As[lk4 + 1][lrow] = av.y;
        As[lk4 + 2][lrow] = av.z;
        As[lk4 + 3][lrow] = av.w;
        Bs[lk4 + 0][lrow] = bv.x;
        Bs[lk4 + 1][lrow] = bv.y;
        Bs[lk4 + 2][lrow] = bv.z;
        Bs[lk4 + 3][lrow] = bv.w;
        __syncthreads();

        #pragma unroll
        for (int kk = 0; kk < 8; kk++) {
            float4 a0 = *(const float4*)&As[kk][ty * 4];
            float4 a1 = *(const float4*)&As[kk][64 + ty * 4];
            float4 b0 = *(const float4*)&Bs[kk][tx * 4];
            float4 b1 = *(const float4*)&Bs[kk][64 + tx * 4];
            unsigned long long bp[4];
            bp[0] = pk2(b0.x, b0.y);
            bp[1] = pk2(b0.z, b0.w);
            bp[2] = pk2(b1.x, b1.y);
            bp[3] = pk2(b1.z, b1.w);
            float ar[8] = {a0.x, a0.y, a0.z, a0.w, a1.x, a1.y, a1.z, a1.w};
            #pragma unroll
            for (int r = 0; r < 8; r++) {
                unsigned long long ap = pk2(ar[r], ar[r]);
                #pragma unroll
                for (int c = 0; c < 4; c++) fma2(acc[r][c], ap, bp[c]);
            }
        }
    }

    // epilogue
    #pragma unroll
    for (int r = 0; r < 8; r++) {
        int m = m0 + ((r < 4) ? (ty * 4 + r) : (64 + ty * 4 + (r - 4)));
        #pragma unroll
        for (int c = 0; c < 4; c++) {
            int n = n0 + ((c < 2) ? (tx * 4 + c * 2) : (64 + tx * 4 + (c - 2) * 2));
            float f0, f1;
            upk2(acc[r][c], f0, f1);
            if (n < Hn)     out[(size_t)m * Hn + n]     = f0 + bias[n];
            if (n + 1 < Hn) out[(size_t)m * Hn + n + 1] = f1 + bias[n + 1];
        }
    }
}

// ---------------------------------------------------------------------------
// Flash attention: one block per (q-tile of 64, head, batch). 512 threads.
// K/V tiles of 32 keys staged in dynamic smem. Online softmax (per-key mask,
// masked value exactly -10000 to match reference). Mask arrives as int32.
// ---------------------------------------------------------------------------
#define ATTN_SMEM_FLOATS (64*126 + 125*32 + 32*128 + 64*33 + 64*3 + 32)
#define ATTN_SMEM_BYTES  (ATTN_SMEM_FLOATS * 4)

__global__ __launch_bounds__(512)
void attn_kernel(const int* __restrict__ mask)
{
    extern __shared__ __align__(16) char smraw[];
    float* Qs  = (float*)smraw;               // [64][126] padded
    float* Kst = Qs  + 64 * 126;              // [125][32] transposed
    float* Vs  = Kst + 125 * 32;              // [32][128] padded (zero-fill)
    float* Ps  = Vs  + 32 * 128;              // [64][33]  padded
    float* m_s = Ps  + 64 * 33;               // [64]
    float* l_s = m_s + 64;                    // [64]
    float* c_s = l_s + 64;                    // [64]
    int*   msk = (int*)(c_s + 64);            // [32]

    const int t    = threadIdx.x;
    const int q0   = blockIdx.x * 64;
    const int h    = blockIdx.y;
    const int b    = blockIdx.z;
    const int qrow = t >> 3;      // 0..63
    const int grp  = t & 7;       // 0..7

    // load Q tile
    for (int e = t; e < 64 * DKn; e += 512) {
        int qq = e / DKn, d = e % DKn;
        Qs[qq * 126 + d] = g_qh[(size_t)(b * Sn + q0 + qq) * Hn + h * DKn + d];
    }
    if (t < 64) { m_s[t] = -1e30f; l_s[t] = 0.f; }

    float zacc[16];
    #pragma unroll
    for (int i = 0; i < 16; i++) zacc[i] = 0.f;

    const float scale = 0.08944271909999159f;   // 1/sqrt(125)

    for (int kt = 0; kt < Sn; kt += 32) {
        __syncthreads();   // prior-iter reads of Kst/Vs/Ps done (and Q load, kt=0)

        // stage K (transposed) and V tiles
        for (int e = t; e < 32 * DKn; e += 512) {
            int j = e / DKn, d = e % DKn;
            size_t base = (size_t)(b * Sn + kt + j) * Hn + h * DKn;
            Kst[d * 32 + j] = g_kh[base + d];
            Vs[j * 128 + d] = g_vh[base + d];
        }
        if (t < 32) {
            Vs[t * 128 + 125] = 0.f;
            Vs[t * 128 + 126] = 0.f;
            Vs[t * 128 + 127] = 0.f;
            msk[t] = mask[b * Sn + kt + t];
        }
        __syncthreads();

        // phase 1: scores (4 per thread)
        {
            const int jb = grp * 4;
            float s0 = 0.f, s1 = 0.f, s2 = 0.f, s3 = 0.f;
            #pragma unroll 5
            for (int d = 0; d < DKn; d++) {
                float qv = Qs[qrow * 126 + d];
                float4 kv = *(const float4*)&Kst[d * 32 + jb];
                s0 += qv * kv.x; s1 += qv * kv.y;
                s2 += qv * kv.z; s3 += qv * kv.w;
            }
            s0 *= scale; s1 *= scale; s2 *= scale; s3 *= scale;
            if (msk[jb + 0] != 0) s0 = -10000.f;
            if (msk[jb + 1] != 0) s1 = -10000.f;
            if (msk[jb + 2] != 0) s2 = -10000.f;
            if (msk[jb + 3] != 0) s3 = -10000.f;
            Ps[qrow * 33 + jb + 0] = s0;
            Ps[qrow * 33 + jb + 1] = s1;
            Ps[qrow * 33 + jb + 2] = s2;
            Ps[qrow * 33 + jb + 3] = s3;
        }
        __syncthreads();

        // phase 2: online softmax bookkeeping (one thread per q row)
        if (t < 64) {
            float mo = m_s[t];
            float tmax = -1e30f;
            #pragma unroll
            for (int j = 0; j < 32; j++) tmax = fmaxf(tmax, Ps[t * 33 + j]);
            float nm   = fmaxf(mo, tmax);
            float corr = __expf(mo - nm);
            float sum  = 0.f;
            #pragma unroll
            for (int j = 0; j < 32; j++) {
                float e = __expf(Ps[t * 33 + j] - nm);
                Ps[t * 33 + j] = e;
                sum += e;
            }
            l_s[t] = l_s[t] * corr + sum;
            m_s[t] = nm;
            c_s[t] = corr;
        }
        __syncthreads();

        // phase 3: z accumulation (thread owns q row x 16-dim chunk)
        {
            float corr = c_s[qrow];
            #pragma unroll
            for (int i = 0; i < 16; i++) zacc[i] *= corr;
            const int d0 = grp * 16;
            #pragma unroll 4
            for (int j = 0; j < 32; j++) {
                float p = Ps[qrow * 33 + j];
                const float* vr = &Vs[j * 128 + d0];
                float4 v0 = *(const float4*)(vr + 0);
                float4 v1 = *(const float4*)(vr + 4);
                float4 v2 = *(const float4*)(vr + 8);
                float4 v3 = *(const float4*)(vr + 12);
                zacc[0]  += p * v0.x; zacc[1]  += p * v0.y;
                zacc[2]  += p * v0.z; zacc[3]  += p * v0.w;
                zacc[4]  += p * v1.x; zacc[5]  += p * v1.y;
                zacc[6]  += p * v1.z; zacc[7]  += p * v1.w;
                zacc[8]  += p * v2.x; zacc[9]  += p * v2.y;
                zacc[10] += p * v2.z; zacc[11] += p * v2.w;
                zacc[12] += p * v3.x; zacc[13] += p * v3.y;
                zacc[14] += p * v3.z; zacc[15] += p * v3.w;
            }
        }
    }

    // write normalized output (l_s final; last phase-3 sync already passed)
    float inv = 1.f / l_s[qrow];
    size_t ob = (size_t)(b * Sn + q0 + qrow) * Hn + h * DKn;
    const int d0 = grp * 16;
    #pragma unroll
    for (int i = 0; i < 16; i++) {
        int d = d0 + i;
        if (d < DKn) g_z[ob + d] = zacc[i] * inv;
    }
}

// ---------------------------------------------------------------------------
// Residual + LayerNorm: out = LN(x + y) * g + b, per row of 1000
// ---------------------------------------------------------------------------
__global__ __launch_bounds__(256)
void ln_kernel(const float* __restrict__ x, const float* __restrict__ y,
               const float* __restrict__ gamma, const float* __restrict__ beta,
               float* __restrict__ out)
{
    __shared__ float buf[Hn];
    __shared__ float red1[8], red2[8];
    __shared__ float mu_s, rs_s;

    const int r = blockIdx.x;
    const int t = threadIdx.x;
    const size_t base = (size_t)r * Hn;

    float s1 = 0.f, s2 = 0.f;
    for (int c = t; c < Hn; c += 256) {
        float vv = x[base + c] + y[base + c];
        buf[c] = vv;
        s1 += vv;
        s2 += vv * vv;
    }
    #pragma unroll
    for (int o = 16; o; o >>= 1) {
        s1 += __shfl_down_sync(0xFFFFFFFFu, s1, o);
        s2 += __shfl_down_sync(0xFFFFFFFFu, s2, o);
    }
    if ((t & 31) == 0) { red1[t >> 5] = s1; red2[t >> 5] = s2; }
    __syncthreads();
    if (t == 0) {
        float a = 0.f, bq = 0.f;
        #pragma unroll
        for (int i = 0; i < 8; i++) { a += red1[i]; bq += red2[i]; }
        float mu  = a * (1.f / Hn);
        float var = bq * (1.f / Hn) - mu * mu;
        mu_s = mu;
        rs_s = rsqrtf(fmaxf(var, 0.f) + 1e-5f);
    }
    __syncthreads();
    float mu = mu_s, rs = rs_s;
    for (int c = t; c < Hn; c += 256)
        out[base + c] = (buf[c] - mu) * rs * gamma[c] + beta[c];
}

// ---------------------------------------------------------------------------
// Host entry
// ---------------------------------------------------------------------------
extern "C" void kernel_launch(void* const* d_in, const int* in_sizes, int n_in,
                              void* d_out, int out_size)
{
    const float* q    = (const float*)d_in[0];
    const float* k    = (const float*)d_in[1];
    const float* v    = (const float*)d_in[2];
    const int*   mask = (const int*)d_in[3];
    const float* Wq_w = (const float*)d_in[4];
    const float* Wq_b = (const float*)d_in[5];
    const float* Wk_w = (const float*)d_in[6];
    const float* Wk_b = (const float*)d_in[7];
    const float* Wv_w = (const float*)d_in[8];
    const float* Wv_b = (const float*)d_in[9];
    const float* Wo_w = (const float*)d_in[10];
    const float* Wo_b = (const float*)d_in[11];
    const float* ln_g = (const float*)d_in[12];
    const float* ln_b = (const float*)d_in[13];
    float* out = (float*)d_out;

    float *qh, *kh, *vh, *z, *y;
    cudaGetSymbolAddress((void**)&qh, g_qh);
    cudaGetSymbolAddress((void**)&kh, g_kh);
    cudaGetSymbolAddress((void**)&vh, g_vh);
    cudaGetSymbolAddress((void**)&z,  g_z);
    cudaGetSymbolAddress((void**)&y,  g_y);

    dim3 gg(8, Mrows / 128);   // N-tiles (ceil(1000/128)=8), M-tiles (512)

    gemm_xwT_kernel<<<gg, 256>>>(q, Wq_w, Wq_b, qh);
    gemm_xwT_kernel<<<gg, 256>>>(k, Wk_w, Wk_b, kh);
    gemm_xwT_kernel<<<gg, 256>>>(v, Wv_w, Wv_b, vh);

    cudaFuncSetAttribute(attn_kernel,
                         cudaFuncAttributeMaxDynamicSharedMemorySize,
                         ATTN_SMEM_BYTES);
    attn_kernel<<<dim3(Sn / 64, NHn, Bn), 512, ATTN_SMEM_BYTES>>>(mask);

    gemm_xwT_kernel<<<gg, 256>>>(z, Wo_w, Wo_b, y);

    ln_kernel<<<Mrows, 256>>>(q, y, ln_g, ln_b, out);
}

// round 3
// speedup vs baseline: 1.2446x; 1.2446x over previous
#include <cuda_runtime.h>
#include <cstdint>

// Problem constants
#define Bn   128
#define Sn   512
#define Hn   1000
#define NHn  8
#define DKn  125
#define Mrows (Bn * Sn)        // 65536

// ---------------------------------------------------------------------------
// Scratch (device globals; allocation in kernel_launch is forbidden)
// ---------------------------------------------------------------------------
__device__ __align__(16) float g_qh[(size_t)Mrows * Hn];
__device__ __align__(16) float g_kh[(size_t)Mrows * Hn];
__device__ __align__(16) float g_vh[(size_t)Mrows * Hn];
__device__ __align__(16) float g_z [(size_t)Mrows * Hn];
__device__ __align__(16) float g_y [(size_t)Mrows * Hn];

// ---------------------------------------------------------------------------
// TF32 tensor-core GEMM: out[M,1000] = X[M,1000] @ W[1000,1000]^T + bias
//   CTA tile 128x128, BK=40 (25 exact K-steps), 8 warps (4x2), warp tile 32x64
//   mma.sync m16n8k8 tf32, fp32 accumulate. cp.async double-buffered smem.
//   smem row stride 44 floats -> conflict-free fragment LDS.
// ---------------------------------------------------------------------------
#define GBK     40
#define GSTR    44                      // padded floats per row
#define GTILE   (128 * GSTR)            // 5632 floats per matrix tile
#define GBUF    (2 * GTILE)             // A + B per buffer
#define GSMEM_FLOATS (2 * GBUF)
#define GSMEM_BYTES  (GSMEM_FLOATS * 4) // 90112

__device__ __forceinline__ void cp16(float* smem_dst, const float* gsrc, bool valid) {
    uint32_t sa = (uint32_t)__cvta_generic_to_shared(smem_dst);
    int sz = valid ? 16 : 0;
    asm volatile("cp.async.ca.shared.global [%0], [%1], 16, %2;\n"
                 :: "r"(sa), "l"(gsrc), "r"(sz));
}
__device__ __forceinline__ uint32_t f2tf32(float f) {
    uint32_t r;
    asm("cvt.rna.tf32.f32 %0, %1;" : "=r"(r) : "f"(f));
    return r;
}
__device__ __forceinline__ void mma_tf32(float* d, const uint32_t* a,
                                         uint32_t b0, uint32_t b1) {
    asm volatile(
        "mma.sync.aligned.m16n8k8.row.col.f32.tf32.tf32.f32 "
        "{%0,%1,%2,%3}, {%4,%5,%6,%7}, {%8,%9}, {%0,%1,%2,%3};"
        : "+f"(d[0]), "+f"(d[1]), "+f"(d[2]), "+f"(d[3])
        : "r"(a[0]), "r"(a[1]), "r"(a[2]), "r"(a[3]), "r"(b0), "r"(b1));
}

__global__ __launch_bounds__(256)
void gemm_tc_kernel(const float* __restrict__ X,
                    const float* __restrict__ W,
                    const float* __restrict__ bias,
                    float* __restrict__ out)
{
    extern __shared__ __align__(16) float sm[];

    const int t      = threadIdx.x;
    const int warp   = t >> 5;
    const int lane   = t & 31;
    const int warp_m = warp >> 1;    // 0..3
    const int warp_n = warp & 1;     // 0..1
    const int g      = lane >> 2;    // 0..7
    const int tig    = lane & 3;     // 0..3
    const int m0     = blockIdx.y * 128;
    const int n0     = blockIdx.x * 128;

    float acc[2][8][4];
    #pragma unroll
    for (int mi = 0; mi < 2; mi++)
        #pragma unroll
        for (int ni = 0; ni < 8; ni++)
            #pragma unroll
            for (int c = 0; c < 4; c++) acc[mi][ni][c] = 0.f;

    // ---- async tile loader: A rows always valid; B rows guarded (N=1000) ----
    auto issue_tile = [&](int step, int buf) {
        float* dstA = sm + buf * GBUF;
        float* dstB = dstA + GTILE;
        const int k0 = step * GBK;
        #pragma unroll
        for (int i = 0; i < 5; i++) {
            int id  = t + i * 256;           // 0..1279
            int row = id / 10;
            int seg = id % 10;               // 16B chunk within the 40-float row
            cp16(dstA + row * GSTR + seg * 4,
                 X + (size_t)(m0 + row) * Hn + k0 + seg * 4, true);
            cp16(dstB + row * GSTR + seg * 4,
                 W + (size_t)(n0 + row) * Hn + k0 + seg * 4, (n0 + row) < Hn);
        }
        asm volatile("cp.async.commit_group;\n");
    };

    issue_tile(0, 0);

    for (int s = 0; s < 25; s++) {
        if (s + 1 < 25) {
            issue_tile(s + 1, (s + 1) & 1);
            asm volatile("cp.async.wait_group 1;\n");
        } else {
            asm volatile("cp.async.wait_group 0;\n");
        }
        __syncthreads();

        const float* As = sm + (s & 1) * GBUF + (warp_m * 32) * GSTR;
        const float* Bs = sm + (s & 1) * GBUF + GTILE + (warp_n * 64) * GSTR;

        #pragma unroll
        for (int kk = 0; kk < 5; kk++) {
            const int kb = kk * 8;
            uint32_t a[2][4];
            #pragma unroll
            for (int mi = 0; mi < 2; mi++) {
                const int r = mi * 16 + g;
                a[mi][0] = f2tf32(As[(r    ) * GSTR + kb + tig    ]);
                a[mi][1] = f2tf32(As[(r + 8) * GSTR + kb + tig    ]);
                a[mi][2] = f2tf32(As[(r    ) * GSTR + kb + tig + 4]);
                a[mi][3] = f2tf32(As[(r + 8) * GSTR + kb + tig + 4]);
            }
            #pragma unroll
            for (int ni = 0; ni < 8; ni++) {
                const int rb = ni * 8 + g;
                uint32_t b0 = f2tf32(Bs[rb * GSTR + kb + tig    ]);
                uint32_t b1 = f2tf32(Bs[rb * GSTR + kb + tig + 4]);
                mma_tf32(acc[0][ni], a[0], b0, b1);
                mma_tf32(acc[1][ni], a[1], b0, b1);
            }
        }
        __syncthreads();
    }

    // ---- epilogue: +bias, guarded float2 stores ----
    #pragma unroll
    for (int mi = 0; mi < 2; mi++) {
        const int row = m0 + warp_m * 32 + mi * 16 + g;
        #pragma unroll
        for (int ni = 0; ni < 8; ni++) {
            const int col = n0 + warp_n * 64 + ni * 8 + tig * 2;
            if (col < Hn) {
                float2 bb = *(const float2*)(bias + col);
                float2 r0 = make_float2(acc[mi][ni][0] + bb.x,
                                        acc[mi][ni][1] + bb.y);
                float2 r1 = make_float2(acc[mi][ni][2] + bb.x,
                                        acc[mi][ni][3] + bb.y);
                *(float2*)(out + (size_t)row * Hn + col)       = r0;
                *(float2*)(out + (size_t)(row + 8) * Hn + col) = r1;
            }
        }
    }
}

// ---------------------------------------------------------------------------
// Flash attention: one block per (q-tile of 64, head, batch). 512 threads.
// K/V tiles of 32 keys staged in dynamic smem. Online softmax (per-key mask,
// masked value exactly -10000 to match reference). Mask arrives as int32.
// ---------------------------------------------------------------------------
#define ATTN_SMEM_FLOATS (64*126 + 125*32 + 32*128 + 64*33 + 64*3 + 32)
#define ATTN_SMEM_BYTES  (ATTN_SMEM_FLOATS * 4)

__global__ __launch_bounds__(512)
void attn_kernel(const int* __restrict__ mask)
{
    extern __shared__ __align__(16) char smraw[];
    float* Qs  = (float*)smraw;               // [64][126] padded
    float* Kst = Qs  + 64 * 126;              // [125][32] transposed
    float* Vs  = Kst + 125 * 32;              // [32][128] padded (zero-fill)
    float* Ps  = Vs  + 32 * 128;              // [64][33]  padded
    float* m_s = Ps  + 64 * 33;               // [64]
    float* l_s = m_s + 64;                    // [64]
    float* c_s = l_s + 64;                    // [64]
    int*   msk = (int*)(c_s + 64);            // [32]

    const int t    = threadIdx.x;
    const int q0   = blockIdx.x * 64;
    const int h    = blockIdx.y;
    const int b    = blockIdx.z;
    const int qrow = t >> 3;      // 0..63
    const int grp  = t & 7;       // 0..7

    // load Q tile
    for (int e = t; e < 64 * DKn; e += 512) {
        int qq = e / DKn, d = e % DKn;
        Qs[qq * 126 + d] = g_qh[(size_t)(b * Sn + q0 + qq) * Hn + h * DKn + d];
    }
    if (t < 64) { m_s[t] = -1e30f; l_s[t] = 0.f; }

    float zacc[16];
    #pragma unroll
    for (int i = 0; i < 16; i++) zacc[i] = 0.f;

    const float scale = 0.08944271909999159f;   // 1/sqrt(125)

    for (int kt = 0; kt < Sn; kt += 32) {
        __syncthreads();   // prior-iter reads of Kst/Vs/Ps done (and Q load, kt=0)

        // stage K (transposed) and V tiles
        for (int e = t; e < 32 * DKn; e += 512) {
            int j = e / DKn, d = e % DKn;
            size_t base = (size_t)(b * Sn + kt + j) * Hn + h * DKn;
            Kst[d * 32 + j] = g_kh[base + d];
            Vs[j * 128 + d] = g_vh[base + d];
        }
        if (t < 32) {
            Vs[t * 128 + 125] = 0.f;
            Vs[t * 128 + 126] = 0.f;
            Vs[t * 128 + 127] = 0.f;
            msk[t] = mask[b * Sn + kt + t];
        }
        __syncthreads();

        // phase 1: scores (4 per thread)
        {
            const int jb = grp * 4;
            float s0 = 0.f, s1 = 0.f, s2 = 0.f, s3 = 0.f;
            #pragma unroll 5
            for (int d = 0; d < DKn; d++) {
                float qv = Qs[qrow * 126 + d];
                float4 kv = *(const float4*)&Kst[d * 32 + jb];
                s0 += qv * kv.x; s1 += qv * kv.y;
                s2 += qv * kv.z; s3 += qv * kv.w;
            }
            s0 *= scale; s1 *= scale; s2 *= scale; s3 *= scale;
            if (msk[jb + 0] != 0) s0 = -10000.f;
            if (msk[jb + 1] != 0) s1 = -10000.f;
            if (msk[jb + 2] != 0) s2 = -10000.f;
            if (msk[jb + 3] != 0) s3 = -10000.f;
            Ps[qrow * 33 + jb + 0] = s0;
            Ps[qrow * 33 + jb + 1] = s1;
            Ps[qrow * 33 + jb + 2] = s2;
            Ps[qrow * 33 + jb + 3] = s3;
        }
        __syncthreads();

        // phase 2: online softmax bookkeeping (one thread per q row)
        if (t < 64) {
            float mo = m_s[t];
            float tmax = -1e30f;
            #pragma unroll
            for (int j = 0; j < 32; j++) tmax = fmaxf(tmax, Ps[t * 33 + j]);
            float nm   = fmaxf(mo, tmax);
            float corr = __expf(mo - nm);
            float sum  = 0.f;
            #pragma unroll
            for (int j = 0; j < 32; j++) {
                float e = __expf(Ps[t * 33 + j] - nm);
                Ps[t * 33 + j] = e;
                sum += e;
            }
            l_s[t] = l_s[t] * corr + sum;
            m_s[t] = nm;
            c_s[t] = corr;
        }
        __syncthreads();

        // phase 3: z accumulation (thread owns q row x 16-dim chunk)
        {
            float corr = c_s[qrow];
            #pragma unroll
            for (int i = 0; i < 16; i++) zacc[i] *= corr;
            const int d0 = grp * 16;
            #pragma unroll 4
            for (int j = 0; j < 32; j++) {
                float p = Ps[qrow * 33 + j];
                const float* vr = &Vs[j * 128 + d0];
                float4 v0 = *(const float4*)(vr + 0);
                float4 v1 = *(const float4*)(vr + 4);
                float4 v2 = *(const float4*)(vr + 8);
                float4 v3 = *(const float4*)(vr + 12);
                zacc[0]  += p * v0.x; zacc[1]  += p * v0.y;
                zacc[2]  += p * v0.z; zacc[3]  += p * v0.w;
                zacc[4]  += p * v1.x; zacc[5]  += p * v1.y;
                zacc[6]  += p * v1.z; zacc[7]  += p * v1.w;
                zacc[8]  += p * v2.x; zacc[9]  += p * v2.y;
                zacc[10] += p * v2.z; zacc[11] += p * v2.w;
                zacc[12] += p * v3.x; zacc[13] += p * v3.y;
                zacc[14] += p * v3.z; zacc[15] += p * v3.w;
            }
        }
    }

    // write normalized output (l_s final; last phase-3 sync already passed)
    float inv = 1.f / l_s[qrow];
    size_t ob = (size_t)(b * Sn + q0 + qrow) * Hn + h * DKn;
    const int d0 = grp * 16;
    #pragma unroll
    for (int i = 0; i < 16; i++) {
        int d = d0 + i;
        if (d < DKn) g_z[ob + d] = zacc[i] * inv;
    }
}

// ---------------------------------------------------------------------------
// Residual + LayerNorm: out = LN(x + y) * g + b, per row of 1000
// ---------------------------------------------------------------------------
__global__ __launch_bounds__(256)
void ln_kernel(const float* __restrict__ x, const float* __restrict__ y,
               const float* __restrict__ gamma, const float* __restrict__ beta,
               float* __restrict__ out)
{
    __shared__ float buf[Hn];
    __shared__ float red1[8], red2[8];
    __shared__ float mu_s, rs_s;

    const int r = blockIdx.x;
    const int t = threadIdx.x;
    const size_t base = (size_t)r * Hn;

    float s1 = 0.f, s2 = 0.f;
    for (int c = t; c < Hn; c += 256) {
        float vv = x[base + c] + y[base + c];
        buf[c] = vv;
        s1 += vv;
        s2 += vv * vv;
    }
    #pragma unroll
    for (int o = 16; o; o >>= 1) {
        s1 += __shfl_down_sync(0xFFFFFFFFu, s1, o);
        s2 += __shfl_down_sync(0xFFFFFFFFu, s2, o);
    }
    if ((t & 31) == 0) { red1[t >> 5] = s1; red2[t >> 5] = s2; }
    __syncthreads();
    if (t == 0) {
        float a = 0.f, bq = 0.f;
        #pragma unroll
        for (int i = 0; i < 8; i++) { a += red1[i]; bq += red2[i]; }
        float mu  = a * (1.f / Hn);
        float var = bq * (1.f / Hn) - mu * mu;
        mu_s = mu;
        rs_s = rsqrtf(fmaxf(var, 0.f) + 1e-5f);
    }
    __syncthreads();
    float mu = mu_s, rs = rs_s;
    for (int c = t; c < Hn; c += 256)
        out[base + c] = (buf[c] - mu) * rs * gamma[c] + beta[c];
}

// ---------------------------------------------------------------------------
// Host entry
// ---------------------------------------------------------------------------
extern "C" void kernel_launch(void* const* d_in, const int* in_sizes, int n_in,
                              void* d_out, int out_size)
{
    const float* q    = (const float*)d_in[0];
    const float* k    = (const float*)d_in[1];
    const float* v    = (const float*)d_in[2];
    const int*   mask = (const int*)d_in[3];
    const float* Wq_w = (const float*)d_in[4];
    const float* Wq_b = (const float*)d_in[5];
    const float* Wk_w = (const float*)d_in[6];
    const float* Wk_b = (const float*)d_in[7];
    const float* Wv_w = (const float*)d_in[8];
    const float* Wv_b = (const float*)d_in[9];
    const float* Wo_w = (const float*)d_in[10];
    const float* Wo_b = (const float*)d_in[11];
    const float* ln_g = (const float*)d_in[12];
    const float* ln_b = (const float*)d_in[13];
    float* out = (float*)d_out;

    float *qh, *kh, *vh, *z, *y;
    cudaGetSymbolAddress((void**)&qh, g_qh);
    cudaGetSymbolAddress((void**)&kh, g_kh);
    cudaGetSymbolAddress((void**)&vh, g_vh);
    cudaGetSymbolAddress((void**)&z,  g_z);
    cudaGetSymbolAddress((void**)&y,  g_y);

    dim3 gg(8, Mrows / 128);   // N-tiles (ceil(1000/128)=8), M-tiles (512)

    cudaFuncSetAttribute(gemm_tc_kernel,
                         cudaFuncAttributeMaxDynamicSharedMemorySize,
                         GSMEM_BYTES);

    gemm_tc_kernel<<<gg, 256, GSMEM_BYTES>>>(q, Wq_w, Wq_b, qh);
    gemm_tc_kernel<<<gg, 256, GSMEM_BYTES>>>(k, Wk_w, Wk_b, kh);
    gemm_tc_kernel<<<gg, 256, GSMEM_BYTES>>>(v, Wv_w, Wv_b, vh);

    cudaFuncSetAttribute(attn_kernel,
                         cudaFuncAttributeMaxDynamicSharedMemorySize,
                         ATTN_SMEM_BYTES);
    attn_kernel<<<dim3(Sn / 64, NHn, Bn), 512, ATTN_SMEM_BYTES>>>(mask);

    gemm_tc_kernel<<<gg, 256, GSMEM_BYTES>>>(z, Wo_w, Wo_b, y);

    ln_kernel<<<Mrows, 256>>>(q, y, ln_g, ln_b, out);
}

// round 5
// speedup vs baseline: 2.2394x; 1.7992x over previous
#include <cuda_runtime.h>
#include <cstdint>

// Problem constants
#define Bn   128
#define Sn   512
#define Hn   1000
#define NHn  8
#define DKn  125
#define Mrows (Bn * Sn)        // 65536

// ---------------------------------------------------------------------------
// Scratch (device globals; allocation in kernel_launch is forbidden)
// ---------------------------------------------------------------------------
__device__ __align__(16) float g_qh[(size_t)Mrows * Hn];
__device__ __align__(16) float g_kh[(size_t)Mrows * Hn];
__device__ __align__(16) float g_vh[(size_t)Mrows * Hn];
__device__ __align__(16) float g_z [(size_t)Mrows * Hn];   // tf32-rounded by attn
__device__ __align__(16) float g_y [(size_t)Mrows * Hn];
__device__ __align__(16) float g_rq[(size_t)Mrows * Hn];
__device__ __align__(16) float g_rk[(size_t)Mrows * Hn];
__device__ __align__(16) float g_rv[(size_t)Mrows * Hn];
__device__ __align__(16) float g_rwq[(size_t)Hn * Hn];
__device__ __align__(16) float g_rwk[(size_t)Hn * Hn];
__device__ __align__(16) float g_rwv[(size_t)Hn * Hn];
__device__ __align__(16) float g_rwo[(size_t)Hn * Hn];

// ---------------------------------------------------------------------------
// helpers
// ---------------------------------------------------------------------------
__device__ __forceinline__ unsigned long long pk2(float lo, float hi) {
    unsigned long long r;
    asm("mov.b64 %0, {%1, %2};" : "=l"(r) : "f"(lo), "f"(hi));
    return r;
}
__device__ __forceinline__ void fma2(unsigned long long &d,
                                     unsigned long long a,
                                     unsigned long long b) {
    asm("fma.rn.f32x2 %0, %1, %2, %0;" : "+l"(d) : "l"(a), "l"(b));
}
__device__ __forceinline__ void mul2(unsigned long long &d,
                                     unsigned long long a) {
    asm("mul.rn.f32x2 %0, %0, %1;" : "+l"(d) : "l"(a));
}
__device__ __forceinline__ void upk2(unsigned long long v, float &lo, float &hi) {
    asm("mov.b64 {%0, %1}, %2;" : "=f"(lo), "=f"(hi) : "l"(v));
}
__device__ __forceinline__ uint32_t f2tf32(float f) {
    uint32_t r;
    asm("cvt.rna.tf32.f32 %0, %1;" : "=r"(r) : "f"(f));
    return r;
}
__device__ __forceinline__ void mma_tf32(float* d, const uint32_t* a,
                                         uint32_t b0, uint32_t b1) {
    asm volatile(
        "mma.sync.aligned.m16n8k8.row.col.f32.tf32.tf32.f32 "
        "{%0,%1,%2,%3}, {%4,%5,%6,%7}, {%8,%9}, {%0,%1,%2,%3};"
        : "+f"(d[0]), "+f"(d[1]), "+f"(d[2]), "+f"(d[3])
        : "r"(a[0]), "r"(a[1]), "r"(a[2]), "r"(a[3]), "r"(b0), "r"(b1));
}
__device__ __forceinline__ void cp16(float* smem_dst, const float* gsrc, bool valid) {
    uint32_t sa = (uint32_t)__cvta_generic_to_shared(smem_dst);
    int sz = valid ? 16 : 0;
    asm volatile("cp.async.ca.shared.global [%0], [%1], 16, %2;\n"
                 :: "r"(sa), "l"(gsrc), "r"(sz));
}

// ---------------------------------------------------------------------------
// tf32 pre-rounding (rna)
// ---------------------------------------------------------------------------
__global__ __launch_bounds__(256)
void round_tf32_kernel(const float* __restrict__ in, float* __restrict__ out, int n4)
{
    int i = blockIdx.x * 256 + threadIdx.x;
    if (i >= n4) return;
    float4 v = ((const float4*)in)[i];
    uint32_t a = f2tf32(v.x), b = f2tf32(v.y), c = f2tf32(v.z), d = f2tf32(v.w);
    ((float4*)out)[i] = make_float4(__uint_as_float(a), __uint_as_float(b),
                                    __uint_as_float(c), __uint_as_float(d));
}

// ---------------------------------------------------------------------------
// TF32 mma.sync GEMM: out[M,1000] = X[M,1000] @ W[1000,1000]^T + bias
//   CTA tile 256x128, warp tile 64x64 (8 warps 4x2), BK=40 (25 exact tiles),
//   3-stage cp.async pipeline, ONE __syncthreads per K-tile.
//   Operands pre-rounded to tf32 -> fragments loaded as raw u32 (no cvt).
// ---------------------------------------------------------------------------
#define GSTR  44                          // padded floats per 40-float row
#define GA_FL (256 * GSTR)                // 11264 floats
#define GB_FL (128 * GSTR)                // 5632 floats
#define GSTAGE_FL (GA_FL + GB_FL)         // 16896 floats
#define GSMEM_BYTES (3 * GSTAGE_FL * 4)   // 202752 bytes

__global__ __launch_bounds__(256)
void gemm_tc_kernel(const float* __restrict__ X,
                    const float* __restrict__ W,
                    const float* __restrict__ bias,
                    float* __restrict__ out)
{
    extern __shared__ __align__(16) float sm[];

    const int t      = threadIdx.x;
    const int warp   = t >> 5;
    const int lane   = t & 31;
    const int warp_m = warp >> 1;    // 0..3  (64 rows each)
    const int warp_n = warp & 1;     // 0..1  (64 cols each)
    const int g      = lane >> 2;    // 0..7
    const int tig    = lane & 3;     // 0..3
    const int m0     = blockIdx.y * 256;
    const int n0     = blockIdx.x * 128;

    float acc[4][8][4];
    #pragma unroll
    for (int mi = 0; mi < 4; mi++)
        #pragma unroll
        for (int ni = 0; ni < 8; ni++)
            #pragma unroll
            for (int c = 0; c < 4; c++) acc[mi][ni][c] = 0.f;

    auto stage = [&](int s) {
        float* base = sm + (s % 3) * GSTAGE_FL;
        float* dA = base;
        float* dB = base + GA_FL;
        const int k0 = s * 40;
        #pragma unroll
        for (int i = 0; i < 10; i++) {            // A: 256 rows x 10 chunks
            int u = t + i * 256;
            int row = u / 10, seg = u % 10;
            cp16(dA + row * GSTR + seg * 4,
                 X + (size_t)(m0 + row) * Hn + k0 + seg * 4, true);
        }
        #pragma unroll
        for (int i = 0; i < 5; i++) {             // B: 128 rows x 10 chunks
            int u = t + i * 256;
            int row = u / 10, seg = u % 10;
            cp16(dB + row * GSTR + seg * 4,
                 W + (size_t)(n0 + row) * Hn + k0 + seg * 4, (n0 + row) < Hn);
        }
        asm volatile("cp.async.commit_group;\n");
    };

    stage(0);
    stage(1);

    for (int s = 0; s < 25; s++) {
        if (s < 24) asm volatile("cp.async.wait_group 1;\n");
        else        asm volatile("cp.async.wait_group 0;\n");
        __syncthreads();
        if (s + 2 < 25) stage(s + 2);   // buffer (s+2)%3: all warps passed compute(s-1)

        const uint32_t* As = (const uint32_t*)(sm + (s % 3) * GSTAGE_FL)
                             + (warp_m * 64) * GSTR;
        const uint32_t* Bs = (const uint32_t*)(sm + (s % 3) * GSTAGE_FL + GA_FL)
                             + (warp_n * 64) * GSTR;

        #pragma unroll
        for (int kk = 0; kk < 5; kk++) {
            const int kb = kk * 8 + tig;
            uint32_t b0[8], b1[8];
            #pragma unroll
            for (int ni = 0; ni < 8; ni++) {
                const int r = ni * 8 + g;
                b0[ni] = Bs[r * GSTR + kb];
                b1[ni] = Bs[r * GSTR + kb + 4];
            }
            #pragma unroll
            for (int mi = 0; mi < 4; mi++) {
                const int r = mi * 16 + g;
                uint32_t a[4];
                a[0] = As[r * GSTR + kb];
                a[1] = As[(r + 8) * GSTR + kb];
                a[2] = As[r * GSTR + kb + 4];
                a[3] = As[(r + 8) * GSTR + kb + 4];
                #pragma unroll
                for (int ni = 0; ni < 8; ni++)
                    mma_tf32(acc[mi][ni], a, b0[ni], b1[ni]);
            }
        }
    }

    // epilogue: +bias, guarded float2 stores (col even, pair stays < 1000)
    #pragma unroll
    for (int mi = 0; mi < 4; mi++) {
        const int row = m0 + warp_m * 64 + mi * 16 + g;
        #pragma unroll
        for (int ni = 0; ni < 8; ni++) {
            const int col = n0 + warp_n * 64 + ni * 8 + tig * 2;
            if (col < Hn) {
                float2 bb = *(const float2*)(bias + col);
                float2 r0 = make_float2(acc[mi][ni][0] + bb.x,
                                        acc[mi][ni][1] + bb.y);
                float2 r1 = make_float2(acc[mi][ni][2] + bb.x,
                                        acc[mi][ni][3] + bb.y);
                *(float2*)(out + (size_t)row * Hn + col)       = r0;
                *(float2*)(out + (size_t)(row + 8) * Hn + col) = r1;
            }
        }
    }
}

// ---------------------------------------------------------------------------
// Flash attention v2: block = (64 q rows, head, batch), 512 threads.
// Thread (qrow=t>>3, grp=t&7) owns keys {grp+8jj} and dim chunks {grp*4+32i}.
// Softmax bookkeeping fully in registers + 8-lane shfl reductions.
// 2 syncthreads per key-tile. f32x2 FMA in both inner loops.
// Output written pre-rounded to tf32 (feeds Wo GEMM directly).
// ---------------------------------------------------------------------------
#define AQS  132   // padded stride (125 -> 132, 16B-aligned, conflict-free)
#define ATTN_SMEM_FLOATS (64*AQS + 32*AQS + 32*AQS + 64*33 + 32)
#define ATTN_SMEM_BYTES  (ATTN_SMEM_FLOATS * 4)

__global__ __launch_bounds__(512)
void attn_kernel(const int* __restrict__ mask)
{
    extern __shared__ __align__(16) char smraw[];
    float* Qs  = (float*)smraw;               // [64][132]
    float* Ks  = Qs + 64 * AQS;               // [32][132] key-major
    float* Vs  = Ks + 32 * AQS;               // [32][132]
    float* Ps  = Vs + 32 * AQS;               // [64][33]
    int*   msk = (int*)(Ps + 64 * 33);        // [32]

    const int t    = threadIdx.x;
    const int q0   = blockIdx.x * 64;
    const int h    = blockIdx.y;
    const int b    = blockIdx.z;
    const int qrow = t >> 3;      // 0..63
    const int grp  = t & 7;       // 0..7

    // stage Q + zero pads (dims 125..131 of Q/K/V stay zero forever)
    for (int e = t; e < 64 * DKn; e += 512) {
        int qq = e / DKn, d = e % DKn;
        Qs[qq * AQS + d] = g_qh[(size_t)(b * Sn + q0 + qq) * Hn + h * DKn + d];
    }
    if (t < 448) { Qs[(t / 7) * AQS + 125 + t % 7] = 0.f; }
    if (t < 224) {
        int r = t / 7, d = 125 + t % 7;
        Ks[r * AQS + d] = 0.f;
        Vs[r * AQS + d] = 0.f;
    }

    float m_reg = -1e30f, l_reg = 0.f;
    unsigned long long z2[8];
    #pragma unroll
    for (int i = 0; i < 8; i++) z2[i] = 0ull;

    const float scale = 0.08944271909999159f;   // 1/sqrt(125)

    for (int kt = 0; kt < Sn; kt += 32) {
        __syncthreads();   // prior iter's reads of Ks/Vs done (and Q staged, kt=0)

        for (int e = t; e < 32 * DKn; e += 512) {
            int j = e / DKn, d = e % DKn;
            size_t base = (size_t)(b * Sn + kt + j) * Hn + h * DKn;
            Ks[j * AQS + d] = g_kh[base + d];
            Vs[j * AQS + d] = g_vh[base + d];
        }
        if (t < 32) msk[t] = mask[b * Sn + kt + t];
        __syncthreads();

        // ---- scores for keys j = grp + 8*jj (f32x2 over dim pairs) ----
        unsigned long long acc2[4] = {0ull, 0ull, 0ull, 0ull};
        const float* qrowp = Qs + qrow * AQS;
        #pragma unroll 3
        for (int d = 0; d < AQS; d += 4) {
            ulonglong2 qq = *(const ulonglong2*)(qrowp + d);
            #pragma unroll
            for (int jj = 0; jj < 4; jj++) {
                ulonglong2 kk = *(const ulonglong2*)(Ks + (grp + 8 * jj) * AQS + d);
                fma2(acc2[jj], qq.x, kk.x);
                fma2(acc2[jj], qq.y, kk.y);
            }
        }
        float s[4];
        #pragma unroll
        for (int jj = 0; jj < 4; jj++) {
            float lo, hi;
            upk2(acc2[jj], lo, hi);
            s[jj] = (lo + hi) * scale;
            if (msk[grp + 8 * jj] != 0) s[jj] = -10000.f;
        }

        // ---- online softmax, register-resident, 8-lane reductions ----
        float tmax = fmaxf(fmaxf(s[0], s[1]), fmaxf(s[2], s[3]));
        tmax = fmaxf(tmax, __shfl_xor_sync(0xFFFFFFFFu, tmax, 1));
        tmax = fmaxf(tmax, __shfl_xor_sync(0xFFFFFFFFu, tmax, 2));
        tmax = fmaxf(tmax, __shfl_xor_sync(0xFFFFFFFFu, tmax, 4));
        float nm   = fmaxf(m_reg, tmax);
        float corr = __expf(m_reg - nm);
        float e0 = __expf(s[0] - nm), e1 = __expf(s[1] - nm);
        float e2 = __expf(s[2] - nm), e3 = __expf(s[3] - nm);
        float ps = e0 + e1 + e2 + e3;
        ps += __shfl_xor_sync(0xFFFFFFFFu, ps, 1);
        ps += __shfl_xor_sync(0xFFFFFFFFu, ps, 2);
        ps += __shfl_xor_sync(0xFFFFFFFFu, ps, 4);
        l_reg = l_reg * corr + ps;
        m_reg = nm;
        Ps[qrow * 33 + grp     ] = e0;
        Ps[qrow * 33 + grp + 8 ] = e1;
        Ps[qrow * 33 + grp + 16] = e2;
        Ps[qrow * 33 + grp + 24] = e3;
        __syncwarp();   // Ps row written by the 8 lanes of this row (same warp)

        // ---- z += P @ V (thread's dims: grp*4 + 32*i, f32x2 pairs) ----
        {
            unsigned long long c2 = pk2(corr, corr);
            #pragma unroll
            for (int i = 0; i < 8; i++) mul2(z2[i], c2);
            const float* prow = Ps + qrow * 33;
            #pragma unroll 4
            for (int j = 0; j < 32; j++) {
                float p = prow[j];
                unsigned long long p2 = pk2(p, p);
                const float* vr = Vs + j * AQS + grp * 4;
                #pragma unroll
                for (int i = 0; i < 4; i++) {
                    ulonglong2 vv = *(const ulonglong2*)(vr + 32 * i);
                    fma2(z2[2 * i],     p2, vv.x);
                    fma2(z2[2 * i + 1], p2, vv.y);
                }
            }
        }
    }

    // ---- normalized output, tf32-rounded (consumed by Wo GEMM) ----
    float inv = 1.f / l_reg;
    size_t ob = (size_t)(b * Sn + q0 + qrow) * Hn + h * DKn;
    #pragma unroll
    for (int i = 0; i < 4; i++) {
        int d = grp * 4 + 32 * i;
        float f0, f1, f2, f3;
        upk2(z2[2 * i], f0, f1);
        upk2(z2[2 * i + 1], f2, f3);
        float r[4] = {f0 * inv, f1 * inv, f2 * inv, f3 * inv};
        #pragma unroll
        for (int c = 0; c < 4; c++) {
            if (d + c < DKn)
                g_z[ob + d + c] = __uint_as_float(f2tf32(r[c]));
        }
    }
}

// ---------------------------------------------------------------------------
// Residual + LayerNorm: out = LN(x + y) * g + b, per row of 1000
// ---------------------------------------------------------------------------
__global__ __launch_bounds__(256)
void ln_kernel(const float* __restrict__ x, const float* __restrict__ y,
               const float* __restrict__ gamma, const float* __restrict__ beta,
               float* __restrict__ out)
{
    __shared__ float buf[Hn];
    __shared__ float red1[8], red2[8];
    __shared__ float mu_s, rs_s;

    const int r = blockIdx.x;
    const int t = threadIdx.x;
    const size_t base = (size_t)r * Hn;

    float s1 = 0.f, s2 = 0.f;
    for (int c = t; c < Hn; c += 256) {
        float vv = x[base + c] + y[base + c];
        buf[c] = vv;
        s1 += vv;
        s2 += vv * vv;
    }
    #pragma unroll
    for (int o = 16; o; o >>= 1) {
        s1 += __shfl_down_sync(0xFFFFFFFFu, s1, o);
        s2 += __shfl_down_sync(0xFFFFFFFFu, s2, o);
    }
    if ((t & 31) == 0) { red1[t >> 5] = s1; red2[t >> 5] = s2; }
    __syncthreads();
    if (t == 0) {
        float a = 0.f, bq = 0.f;
        #pragma unroll
        for (int i = 0; i < 8; i++) { a += red1[i]; bq += red2[i]; }
        float mu  = a * (1.f / Hn);
        float var = bq * (1.f / Hn) - mu * mu;
        mu_s = mu;
        rs_s = rsqrtf(fmaxf(var, 0.f) + 1e-5f);
    }
    __syncthreads();
    float mu = mu_s, rs = rs_s;
    for (int c = t; c < Hn; c += 256)
        out[base + c] = (buf[c] - mu) * rs * gamma[c] + beta[c];
}

// ---------------------------------------------------------------------------
// Host entry
// ---------------------------------------------------------------------------
extern "C" void kernel_launch(void* const* d_in, const int* in_sizes, int n_in,
                              void* d_out, int out_size)
{
    const float* q    = (const float*)d_in[0];
    const float* k    = (const float*)d_in[1];
    const float* v    = (const float*)d_in[2];
    const int*   mask = (const int*)d_in[3];
    const float* Wq_w = (const float*)d_in[4];
    const float* Wq_b = (const float*)d_in[5];
    const float* Wk_w = (const float*)d_in[6];
    const float* Wk_b = (const float*)d_in[7];
    const float* Wv_w = (const float*)d_in[8];
    const float* Wv_b = (const float*)d_in[9];
    const float* Wo_w = (const float*)d_in[10];
    const float* Wo_b = (const float*)d_in[11];
    const float* ln_g = (const float*)d_in[12];
    const float* ln_b = (const float*)d_in[13];
    float* out = (float*)d_out;

    float *qh, *kh, *vh, *z, *y, *rq, *rk, *rv, *rwq, *rwk, *rwv, *rwo;
    cudaGetSymbolAddress((void**)&qh,  g_qh);
    cudaGetSymbolAddress((void**)&kh,  g_kh);
    cudaGetSymbolAddress((void**)&vh,  g_vh);
    cudaGetSymbolAddress((void**)&z,   g_z);
    cudaGetSymbolAddress((void**)&y,   g_y);
    cudaGetSymbolAddress((void**)&rq,  g_rq);
    cudaGetSymbolAddress((void**)&rk,  g_rk);
    cudaGetSymbolAddress((void**)&rv,  g_rv);
    cudaGetSymbolAddress((void**)&rwq, g_rwq);
    cudaGetSymbolAddress((void**)&rwk, g_rwk);
    cudaGetSymbolAddress((void**)&rwv, g_rwv);
    cudaGetSymbolAddress((void**)&rwo, g_rwo);

    const int n4_big = (Mrows * Hn) / 4;
    const int n4_w   = (Hn * Hn) / 4;
    const int gb_big = (n4_big + 255) / 256;
    const int gb_w   = (n4_w + 255) / 256;

    round_tf32_kernel<<<gb_big, 256>>>(q, rq, n4_big);
    round_tf32_kernel<<<gb_big, 256>>>(k, rk, n4_big);
    round_tf32_kernel<<<gb_big, 256>>>(v, rv, n4_big);
    round_tf32_kernel<<<gb_w, 256>>>(Wq_w, rwq, n4_w);
    round_tf32_kernel<<<gb_w, 256>>>(Wk_w, rwk, n4_w);
    round_tf32_kernel<<<gb_w, 256>>>(Wv_w, rwv, n4_w);
    round_tf32_kernel<<<gb_w, 256>>>(Wo_w, rwo, n4_w);

    cudaFuncSetAttribute(gemm_tc_kernel,
                         cudaFuncAttributeMaxDynamicSharedMemorySize,
                         GSMEM_BYTES);
    dim3 gg(8, Mrows / 256);   // 8 N-tiles x 256 M-tiles

    gemm_tc_kernel<<<gg, 256, GSMEM_BYTES>>>(rq, rwq, Wq_b, qh);
    gemm_tc_kernel<<<gg, 256, GSMEM_BYTES>>>(rk, rwk, Wk_b, kh);
    gemm_tc_kernel<<<gg, 256, GSMEM_BYTES>>>(rv, rwv, Wv_b, vh);

    cudaFuncSetAttribute(attn_kernel,
                         cudaFuncAttributeMaxDynamicSharedMemorySize,
                         ATTN_SMEM_BYTES);
    attn_kernel<<<dim3(Sn / 64, NHn, Bn), 512, ATTN_SMEM_BYTES>>>(mask);

    gemm_tc_kernel<<<gg, 256, GSMEM_BYTES>>>(z, rwo, Wo_b, y);

    ln_kernel<<<Mrows, 256>>>(q, y, ln_g, ln_b, out);
}

// round 6
// speedup vs baseline: 2.7187x; 1.2140x over previous
#include <cuda_runtime.h>
#include <cuda_bf16.h>
#include <cstdint>

// Problem constants
#define Bn   128
#define Sn   512
#define Hn   1000
#define NHn  8
#define DKn  125
#define Mrows (Bn * Sn)        // 65536

// ---------------------------------------------------------------------------
// Scratch (device globals; allocation in kernel_launch is forbidden)
// ---------------------------------------------------------------------------
__device__ __align__(16) float g_qh[(size_t)Mrows * Hn];
__device__ __align__(16) float g_kh[(size_t)Mrows * Hn];
__device__ __align__(16) float g_vh[(size_t)Mrows * Hn];
__device__ __align__(16) float g_y [(size_t)Mrows * Hn];
__device__ __align__(16) __nv_bfloat16 g_qb[(size_t)Mrows * Hn];
__device__ __align__(16) __nv_bfloat16 g_kb[(size_t)Mrows * Hn];
__device__ __align__(16) __nv_bfloat16 g_vb[(size_t)Mrows * Hn];
__device__ __align__(16) __nv_bfloat16 g_zb[(size_t)Mrows * Hn];
__device__ __align__(16) __nv_bfloat16 g_wqb[(size_t)Hn * Hn];
__device__ __align__(16) __nv_bfloat16 g_wkb[(size_t)Hn * Hn];
__device__ __align__(16) __nv_bfloat16 g_wvb[(size_t)Hn * Hn];
__device__ __align__(16) __nv_bfloat16 g_wob[(size_t)Hn * Hn];

// ---------------------------------------------------------------------------
// helpers
// ---------------------------------------------------------------------------
__device__ __forceinline__ unsigned long long pk2(float lo, float hi) {
    unsigned long long r;
    asm("mov.b64 %0, {%1, %2};" : "=l"(r) : "f"(lo), "f"(hi));
    return r;
}
__device__ __forceinline__ void fma2(unsigned long long &d,
                                     unsigned long long a,
                                     unsigned long long b) {
    asm("fma.rn.f32x2 %0, %1, %2, %0;" : "+l"(d) : "l"(a), "l"(b));
}
__device__ __forceinline__ void mul2(unsigned long long &d,
                                     unsigned long long a) {
    asm("mul.rn.f32x2 %0, %0, %1;" : "+l"(d) : "l"(a));
}
__device__ __forceinline__ void upk2(unsigned long long v, float &lo, float &hi) {
    asm("mov.b64 {%0, %1}, %2;" : "=f"(lo), "=f"(hi) : "l"(v));
}
__device__ __forceinline__ void mma_bf16(float* d, const uint32_t* a,
                                         uint32_t b0, uint32_t b1) {
    asm volatile(
        "mma.sync.aligned.m16n8k16.row.col.f32.bf16.bf16.f32 "
        "{%0,%1,%2,%3}, {%4,%5,%6,%7}, {%8,%9}, {%0,%1,%2,%3};"
        : "+f"(d[0]), "+f"(d[1]), "+f"(d[2]), "+f"(d[3])
        : "r"(a[0]), "r"(a[1]), "r"(a[2]), "r"(a[3]), "r"(b0), "r"(b1));
}
__device__ __forceinline__ void cp16(char* smem_dst, const void* gsrc, bool valid) {
    uint32_t sa = (uint32_t)__cvta_generic_to_shared(smem_dst);
    int sz = valid ? 16 : 0;
    asm volatile("cp.async.ca.shared.global [%0], [%1], 16, %2;\n"
                 :: "r"(sa), "l"(gsrc), "r"(sz));
}

// ---------------------------------------------------------------------------
// f32 -> bf16 conversion (rn), 8 elements per thread
// ---------------------------------------------------------------------------
__global__ __launch_bounds__(256)
void conv_bf16_kernel(const float* __restrict__ in,
                      __nv_bfloat16* __restrict__ out, int n8)
{
    int i = blockIdx.x * 256 + threadIdx.x;
    if (i >= n8) return;
    float4 v0 = ((const float4*)in)[2 * i];
    float4 v1 = ((const float4*)in)[2 * i + 1];
    __nv_bfloat162 p0 = __floats2bfloat162_rn(v0.x, v0.y);
    __nv_bfloat162 p1 = __floats2bfloat162_rn(v0.z, v0.w);
    __nv_bfloat162 p2 = __floats2bfloat162_rn(v1.x, v1.y);
    __nv_bfloat162 p3 = __floats2bfloat162_rn(v1.z, v1.w);
    uint4 u;
    u.x = *(uint32_t*)&p0; u.y = *(uint32_t*)&p1;
    u.z = *(uint32_t*)&p2; u.w = *(uint32_t*)&p3;
    ((uint4*)out)[i] = u;
}

// ---------------------------------------------------------------------------
// BF16 mma.sync GEMM: out[M,1000] = X[M,1000] @ W[1000,1000]^T + bias (fp32 acc)
//   CTA tile 256x128, warp tile 64x64 (8 warps 4x2), BK=64 bf16 (K pad->1024,
//   16 K-tiles), 3-stage cp.async, one __syncthreads per K-tile.
//   smem row stride 88 bf16 (176B): cp.async 16B-aligned + conflict-free LDS.
// ---------------------------------------------------------------------------
#define GROWB   176                       // bytes per smem row (88 bf16)
#define GA_BYTES (256 * GROWB)            // 45056
#define GB_BYTES (128 * GROWB)            // 22528
#define GSTAGE_BYTES (GA_BYTES + GB_BYTES)// 67584
#define GSMEM_BYTES (3 * GSTAGE_BYTES)    // 202752
#define GKTILES 16

__global__ __launch_bounds__(256)
void gemm_bf16_kernel(const __nv_bfloat16* __restrict__ X,
                      const __nv_bfloat16* __restrict__ W,
                      const float* __restrict__ bias,
                      float* __restrict__ out)
{
    extern __shared__ __align__(16) char sm[];

    const int t      = threadIdx.x;
    const int warp   = t >> 5;
    const int lane   = t & 31;
    const int warp_m = warp >> 1;    // 0..3  (64 rows each)
    const int warp_n = warp & 1;     // 0..1  (64 cols each)
    const int g      = lane >> 2;    // 0..7
    const int tig    = lane & 3;     // 0..3
    const int m0     = blockIdx.y * 256;
    const int n0     = blockIdx.x * 128;

    float acc[4][8][4];
    #pragma unroll
    for (int mi = 0; mi < 4; mi++)
        #pragma unroll
        for (int ni = 0; ni < 8; ni++)
            #pragma unroll
            for (int c = 0; c < 4; c++) acc[mi][ni][c] = 0.f;

    auto stage = [&](int s) {
        char* base = sm + (s % 3) * GSTAGE_BYTES;
        char* dA = base;
        char* dB = base + GA_BYTES;
        const int k0 = s * 64;
        #pragma unroll
        for (int i = 0; i < 8; i++) {             // A: 256 rows x 8 chunks(8 bf16)
            int u = t + i * 256;
            int row = u >> 3, ch = u & 7;
            bool v = (k0 + ch * 8) < Hn;          // 1000 % 8 == 0: no straddle
            cp16(dA + row * GROWB + ch * 16,
                 X + (size_t)(m0 + row) * Hn + k0 + ch * 8, v);
        }
        #pragma unroll
        for (int i = 0; i < 4; i++) {             // B: 128 rows x 8 chunks
            int u = t + i * 256;
            int row = u >> 3, ch = u & 7;
            bool v = ((k0 + ch * 8) < Hn) && ((n0 + row) < Hn);
            cp16(dB + row * GROWB + ch * 16,
                 W + (size_t)(n0 + row) * Hn + k0 + ch * 8, v);
        }
        asm volatile("cp.async.commit_group;\n");
    };

    stage(0);
    stage(1);

    for (int s = 0; s < GKTILES; s++) {
        if (s < GKTILES - 1) asm volatile("cp.async.wait_group 1;\n");
        else                 asm volatile("cp.async.wait_group 0;\n");
        __syncthreads();
        if (s + 2 < GKTILES) stage(s + 2);

        const uint32_t* As = (const uint32_t*)(sm + (s % 3) * GSTAGE_BYTES)
                             + (warp_m * 64) * 44;
        const uint32_t* Bs = (const uint32_t*)(sm + (s % 3) * GSTAGE_BYTES + GA_BYTES)
                             + (warp_n * 64) * 44;

        #pragma unroll
        for (int kk = 0; kk < 4; kk++) {
            const int off = kk * 8 + tig;          // uint32 (bf16-pair) index
            uint32_t b0[8], b1[8];
            #pragma unroll
            for (int ni = 0; ni < 8; ni++) {
                const int r = ni * 8 + g;
                b0[ni] = Bs[r * 44 + off];
                b1[ni] = Bs[r * 44 + off + 4];
            }
            #pragma unroll
            for (int mi = 0; mi < 4; mi++) {
                const int r = mi * 16 + g;
                uint32_t a[4];
                a[0] = As[r * 44 + off];
                a[1] = As[(r + 8) * 44 + off];
                a[2] = As[r * 44 + off + 4];
                a[3] = As[(r + 8) * 44 + off + 4];
                #pragma unroll
                for (int ni = 0; ni < 8; ni++)
                    mma_bf16(acc[mi][ni], a, b0[ni], b1[ni]);
            }
        }
    }

    // epilogue: +bias, guarded float2 stores
    #pragma unroll
    for (int mi = 0; mi < 4; mi++) {
        const int row = m0 + warp_m * 64 + mi * 16 + g;
        #pragma unroll
        for (int ni = 0; ni < 8; ni++) {
            const int col = n0 + warp_n * 64 + ni * 8 + tig * 2;
            if (col < Hn) {
                float2 bb = *(const float2*)(bias + col);
                float2 r0 = make_float2(acc[mi][ni][0] + bb.x,
                                        acc[mi][ni][1] + bb.y);
                float2 r1 = make_float2(acc[mi][ni][2] + bb.x,
                                        acc[mi][ni][3] + bb.y);
                *(float2*)(out + (size_t)row * Hn + col)       = r0;
                *(float2*)(out + (size_t)(row + 8) * Hn + col) = r1;
            }
        }
    }
}

// ---------------------------------------------------------------------------
// Flash attention: block = (64 q rows, head, batch), 512 threads.
// fp32 SIMT with f32x2 FMA; register softmax + 8-lane shfl reductions.
// Output written as bf16 (feeds Wo GEMM directly).
// ---------------------------------------------------------------------------
#define AQS  132
#define ATTN_SMEM_FLOATS (64*AQS + 32*AQS + 32*AQS + 64*33 + 32)
#define ATTN_SMEM_BYTES  (ATTN_SMEM_FLOATS * 4)

__global__ __launch_bounds__(512)
void attn_kernel(const int* __restrict__ mask)
{
    extern __shared__ __align__(16) char smraw[];
    float* Qs  = (float*)smraw;               // [64][132]
    float* Ks  = Qs + 64 * AQS;               // [32][132]
    float* Vs  = Ks + 32 * AQS;               // [32][132]
    float* Ps  = Vs + 32 * AQS;               // [64][33]
    int*   msk = (int*)(Ps + 64 * 33);        // [32]

    const int t    = threadIdx.x;
    const int q0   = blockIdx.x * 64;
    const int h    = blockIdx.y;
    const int b    = blockIdx.z;
    const int qrow = t >> 3;      // 0..63
    const int grp  = t & 7;       // 0..7

    for (int e = t; e < 64 * DKn; e += 512) {
        int qq = e / DKn, d = e % DKn;
        Qs[qq * AQS + d] = g_qh[(size_t)(b * Sn + q0 + qq) * Hn + h * DKn + d];
    }
    if (t < 448) { Qs[(t / 7) * AQS + 125 + t % 7] = 0.f; }
    if (t < 224) {
        int r = t / 7, d = 125 + t % 7;
        Ks[r * AQS + d] = 0.f;
        Vs[r * AQS + d] = 0.f;
    }

    float m_reg = -1e30f, l_reg = 0.f;
    unsigned long long z2[8];
    #pragma unroll
    for (int i = 0; i < 8; i++) z2[i] = 0ull;

    const float scale = 0.08944271909999159f;   // 1/sqrt(125)

    for (int kt = 0; kt < Sn; kt += 32) {
        __syncthreads();

        for (int e = t; e < 32 * DKn; e += 512) {
            int j = e / DKn, d = e % DKn;
            size_t base = (size_t)(b * Sn + kt + j) * Hn + h * DKn;
            Ks[j * AQS + d] = g_kh[base + d];
            Vs[j * AQS + d] = g_vh[base + d];
        }
        if (t < 32) msk[t] = mask[b * Sn + kt + t];
        __syncthreads();

        // scores for keys j = grp + 8*jj
        unsigned long long acc2[4] = {0ull, 0ull, 0ull, 0ull};
        const float* qrowp = Qs + qrow * AQS;
        #pragma unroll 3
        for (int d = 0; d < AQS; d += 4) {
            ulonglong2 qq = *(const ulonglong2*)(qrowp + d);
            #pragma unroll
            for (int jj = 0; jj < 4; jj++) {
                ulonglong2 kk = *(const ulonglong2*)(Ks + (grp + 8 * jj) * AQS + d);
                fma2(acc2[jj], qq.x, kk.x);
                fma2(acc2[jj], qq.y, kk.y);
            }
        }
        float s[4];
        #pragma unroll
        for (int jj = 0; jj < 4; jj++) {
            float lo, hi;
            upk2(acc2[jj], lo, hi);
            s[jj] = (lo + hi) * scale;
            if (msk[grp + 8 * jj] != 0) s[jj] = -10000.f;
        }

        // online softmax (registers + 8-lane shfl)
        float tmax = fmaxf(fmaxf(s[0], s[1]), fmaxf(s[2], s[3]));
        tmax = fmaxf(tmax, __shfl_xor_sync(0xFFFFFFFFu, tmax, 1));
        tmax = fmaxf(tmax, __shfl_xor_sync(0xFFFFFFFFu, tmax, 2));
        tmax = fmaxf(tmax, __shfl_xor_sync(0xFFFFFFFFu, tmax, 4));
        float nm   = fmaxf(m_reg, tmax);
        float corr = __expf(m_reg - nm);
        float e0 = __expf(s[0] - nm), e1 = __expf(s[1] - nm);
        float e2 = __expf(s[2] - nm), e3 = __expf(s[3] - nm);
        float ps = e0 + e1 + e2 + e3;
        ps += __shfl_xor_sync(0xFFFFFFFFu, ps, 1);
        ps += __shfl_xor_sync(0xFFFFFFFFu, ps, 2);
        ps += __shfl_xor_sync(0xFFFFFFFFu, ps, 4);
        l_reg = l_reg * corr + ps;
        m_reg = nm;
        Ps[qrow * 33 + grp     ] = e0;
        Ps[qrow * 33 + grp + 8 ] = e1;
        Ps[qrow * 33 + grp + 16] = e2;
        Ps[qrow * 33 + grp + 24] = e3;
        __syncwarp();

        // z += P @ V
        {
            unsigned long long c2 = pk2(corr, corr);
            #pragma unroll
            for (int i = 0; i < 8; i++) mul2(z2[i], c2);
            const float* prow = Ps + qrow * 33;
            #pragma unroll 4
            for (int j = 0; j < 32; j++) {
                float p = prow[j];
                unsigned long long p2 = pk2(p, p);
                const float* vr = Vs + j * AQS + grp * 4;
                #pragma unroll
                for (int i = 0; i < 4; i++) {
                    ulonglong2 vv = *(const ulonglong2*)(vr + 32 * i);
                    fma2(z2[2 * i],     p2, vv.x);
                    fma2(z2[2 * i + 1], p2, vv.y);
                }
            }
        }
    }

    // normalized output -> bf16 (consumed by Wo GEMM)
    float inv = 1.f / l_reg;
    size_t ob = (size_t)(b * Sn + q0 + qrow) * Hn + h * DKn;
    #pragma unroll
    for (int i = 0; i < 4; i++) {
        int d = grp * 4 + 32 * i;
        float f0, f1, f2, f3;
        upk2(z2[2 * i], f0, f1);
        upk2(z2[2 * i + 1], f2, f3);
        float r[4] = {f0 * inv, f1 * inv, f2 * inv, f3 * inv};
        #pragma unroll
        for (int c = 0; c < 4; c++) {
            if (d + c < DKn)
                g_zb[ob + d + c] = __float2bfloat16_rn(r[c]);
        }
    }
}

// ---------------------------------------------------------------------------
// Residual + LayerNorm: out = LN(x + y) * g + b, per row of 1000
// ---------------------------------------------------------------------------
__global__ __launch_bounds__(256)
void ln_kernel(const float* __restrict__ x, const float* __restrict__ y,
               const float* __restrict__ gamma, const float* __restrict__ beta,
               float* __restrict__ out)
{
    __shared__ float buf[Hn];
    __shared__ float red1[8], red2[8];
    __shared__ float mu_s, rs_s;

    const int r = blockIdx.x;
    const int t = threadIdx.x;
    const size_t base = (size_t)r * Hn;

    float s1 = 0.f, s2 = 0.f;
    for (int c = t; c < Hn; c += 256) {
        float vv = x[base + c] + y[base + c];
        buf[c] = vv;
        s1 += vv;
        s2 += vv * vv;
    }
    #pragma unroll
    for (int o = 16; o; o >>= 1) {
        s1 += __shfl_down_sync(0xFFFFFFFFu, s1, o);
        s2 += __shfl_down_sync(0xFFFFFFFFu, s2, o);
    }
    if ((t & 31) == 0) { red1[t >> 5] = s1; red2[t >> 5] = s2; }
    __syncthreads();
    if (t == 0) {
        float a = 0.f, bq = 0.f;
        #pragma unroll
        for (int i = 0; i < 8; i++) { a += red1[i]; bq += red2[i]; }
        float mu  = a * (1.f / Hn);
        float var = bq * (1.f / Hn) - mu * mu;
        mu_s = mu;
        rs_s = rsqrtf(fmaxf(var, 0.f) + 1e-5f);
    }
    __syncthreads();
    float mu = mu_s, rs = rs_s;
    for (int c = t; c < Hn; c += 256)
        out[base + c] = (buf[c] - mu) * rs * gamma[c] + beta[c];
}

// ---------------------------------------------------------------------------
// Host entry
// ---------------------------------------------------------------------------
extern "C" void kernel_launch(void* const* d_in, const int* in_sizes, int n_in,
                              void* d_out, int out_size)
{
    const float* q    = (const float*)d_in[0];
    const float* k    = (const float*)d_in[1];
    const float* v    = (const float*)d_in[2];
    const int*   mask = (const int*)d_in[3];
    const float* Wq_w = (const float*)d_in[4];
    const float* Wq_b = (const float*)d_in[5];
    const float* Wk_w = (const float*)d_in[6];
    const float* Wk_b = (const float*)d_in[7];
    const float* Wv_w = (const float*)d_in[8];
    const float* Wv_b = (const float*)d_in[9];
    const float* Wo_w = (const float*)d_in[10];
    const float* Wo_b = (const float*)d_in[11];
    const float* ln_g = (const float*)d_in[12];
    const float* ln_b = (const float*)d_in[13];
    float* out = (float*)d_out;

    float *qh, *kh, *vh, *y;
    __nv_bfloat16 *qb, *kb, *vb, *zb, *wqb, *wkb, *wvb, *wob;
    cudaGetSymbolAddress((void**)&qh,  g_qh);
    cudaGetSymbolAddress((void**)&kh,  g_kh);
    cudaGetSymbolAddress((void**)&vh,  g_vh);
    cudaGetSymbolAddress((void**)&y,   g_y);
    cudaGetSymbolAddress((void**)&qb,  g_qb);
    cudaGetSymbolAddress((void**)&kb,  g_kb);
    cudaGetSymbolAddress((void**)&vb,  g_vb);
    cudaGetSymbolAddress((void**)&zb,  g_zb);
    cudaGetSymbolAddress((void**)&wqb, g_wqb);
    cudaGetSymbolAddress((void**)&wkb, g_wkb);
    cudaGetSymbolAddress((void**)&wvb, g_wvb);
    cudaGetSymbolAddress((void**)&wob, g_wob);

    const int n8_big = (Mrows * Hn) / 8;      // 8,192,000
    const int n8_w   = (Hn * Hn) / 8;         // 125,000
    const int gb_big = (n8_big + 255) / 256;
    const int gb_w   = (n8_w + 255) / 256;

    conv_bf16_kernel<<<gb_big, 256>>>(q, qb, n8_big);
    conv_bf16_kernel<<<gb_big, 256>>>(k, kb, n8_big);
    conv_bf16_kernel<<<gb_big, 256>>>(v, vb, n8_big);
    conv_bf16_kernel<<<gb_w, 256>>>(Wq_w, wqb, n8_w);
    conv_bf16_kernel<<<gb_w, 256>>>(Wk_w, wkb, n8_w);
    conv_bf16_kernel<<<gb_w, 256>>>(Wv_w, wvb, n8_w);
    conv_bf16_kernel<<<gb_w, 256>>>(Wo_w, wob, n8_w);

    cudaFuncSetAttribute(gemm_bf16_kernel,
                         cudaFuncAttributeMaxDynamicSharedMemorySize,
                         GSMEM_BYTES);
    dim3 gg(8, Mrows / 256);   // 8 N-tiles x 256 M-tiles

    gemm_bf16_kernel<<<gg, 256, GSMEM_BYTES>>>(qb, wqb, Wq_b, qh);
    gemm_bf16_kernel<<<gg, 256, GSMEM_BYTES>>>(kb, wkb, Wk_b, kh);
    gemm_bf16_kernel<<<gg, 256, GSMEM_BYTES>>>(vb, wvb, Wv_b, vh);

    cudaFuncSetAttribute(attn_kernel,
                         cudaFuncAttributeMaxDynamicSharedMemorySize,
                         ATTN_SMEM_BYTES);
    attn_kernel<<<dim3(Sn / 64, NHn, Bn), 512, ATTN_SMEM_BYTES>>>(mask);

    gemm_bf16_kernel<<<gg, 256, GSMEM_BYTES>>>(zb, wob, Wo_b, y);

    ln_kernel<<<Mrows, 256>>>(q, y, ln_g, ln_b, out);
}

// round 7
// speedup vs baseline: 2.8999x; 1.0667x over previous
#include <cuda_runtime.h>
#include <cuda_bf16.h>
#include <cstdint>

// Problem constants
#define Bn   128
#define Sn   512
#define Hn   1000
#define NHn  8
#define DKn  125
#define Mrows (Bn * Sn)        // 65536

// ---------------------------------------------------------------------------
// Scratch (device globals; allocation in kernel_launch is forbidden)
// ---------------------------------------------------------------------------
__device__ __align__(16) float g_qh[(size_t)Mrows * Hn];
__device__ __align__(16) float g_kh[(size_t)Mrows * Hn];
__device__ __align__(16) float g_vh[(size_t)Mrows * Hn];
__device__ __align__(16) float g_y [(size_t)Mrows * Hn];
__device__ __align__(16) __nv_bfloat16 g_qb[(size_t)Mrows * Hn];
__device__ __align__(16) __nv_bfloat16 g_kb[(size_t)Mrows * Hn];
__device__ __align__(16) __nv_bfloat16 g_vb[(size_t)Mrows * Hn];
__device__ __align__(16) __nv_bfloat16 g_zb[(size_t)Mrows * Hn];
__device__ __align__(16) __nv_bfloat16 g_wqb[(size_t)Hn * Hn];
__device__ __align__(16) __nv_bfloat16 g_wkb[(size_t)Hn * Hn];
__device__ __align__(16) __nv_bfloat16 g_wvb[(size_t)Hn * Hn];
__device__ __align__(16) __nv_bfloat16 g_wob[(size_t)Hn * Hn];

// ---------------------------------------------------------------------------
// helpers
// ---------------------------------------------------------------------------
__device__ __forceinline__ unsigned long long pk2(float lo, float hi) {
    unsigned long long r;
    asm("mov.b64 %0, {%1, %2};" : "=l"(r) : "f"(lo), "f"(hi));
    return r;
}
__device__ __forceinline__ void fma2(unsigned long long &d,
                                     unsigned long long a,
                                     unsigned long long b) {
    asm("fma.rn.f32x2 %0, %1, %2, %0;" : "+l"(d) : "l"(a), "l"(b));
}
__device__ __forceinline__ void mul2(unsigned long long &d,
                                     unsigned long long a) {
    asm("mul.rn.f32x2 %0, %0, %1;" : "+l"(d) : "l"(a));
}
__device__ __forceinline__ void upk2(unsigned long long v, float &lo, float &hi) {
    asm("mov.b64 {%0, %1}, %2;" : "=f"(lo), "=f"(hi) : "l"(v));
}
__device__ __forceinline__ void mma_bf16(float* d, const uint32_t* a,
                                         uint32_t b0, uint32_t b1) {
    asm volatile(
        "mma.sync.aligned.m16n8k16.row.col.f32.bf16.bf16.f32 "
        "{%0,%1,%2,%3}, {%4,%5,%6,%7}, {%8,%9}, {%0,%1,%2,%3};"
        : "+f"(d[0]), "+f"(d[1]), "+f"(d[2]), "+f"(d[3])
        : "r"(a[0]), "r"(a[1]), "r"(a[2]), "r"(a[3]), "r"(b0), "r"(b1));
}
__device__ __forceinline__ void ldsm_x4(uint32_t &r0, uint32_t &r1,
                                        uint32_t &r2, uint32_t &r3,
                                        uint32_t addr) {
    asm volatile("ldmatrix.sync.aligned.m8n8.x4.shared.b16 {%0,%1,%2,%3}, [%4];"
                 : "=r"(r0), "=r"(r1), "=r"(r2), "=r"(r3) : "r"(addr));
}
__device__ __forceinline__ void cp16(char* smem_dst, const void* gsrc, bool valid) {
    uint32_t sa = (uint32_t)__cvta_generic_to_shared(smem_dst);
    int sz = valid ? 16 : 0;
    asm volatile("cp.async.ca.shared.global [%0], [%1], 16, %2;\n"
                 :: "r"(sa), "l"(gsrc), "r"(sz));
}

// ---------------------------------------------------------------------------
// f32 -> bf16 conversion (rn), 8 elements per thread
// ---------------------------------------------------------------------------
__global__ __launch_bounds__(256)
void conv_bf16_kernel(const float* __restrict__ in,
                      __nv_bfloat16* __restrict__ out, int n8)
{
    int i = blockIdx.x * 256 + threadIdx.x;
    if (i >= n8) return;
    float4 v0 = ((const float4*)in)[2 * i];
    float4 v1 = ((const float4*)in)[2 * i + 1];
    __nv_bfloat162 p0 = __floats2bfloat162_rn(v0.x, v0.y);
    __nv_bfloat162 p1 = __floats2bfloat162_rn(v0.z, v0.w);
    __nv_bfloat162 p2 = __floats2bfloat162_rn(v1.x, v1.y);
    __nv_bfloat162 p3 = __floats2bfloat162_rn(v1.z, v1.w);
    uint4 u;
    u.x = *(uint32_t*)&p0; u.y = *(uint32_t*)&p1;
    u.z = *(uint32_t*)&p2; u.w = *(uint32_t*)&p3;
    ((uint4*)out)[i] = u;
}

// ---------------------------------------------------------------------------
// BF16 mma.sync GEMM: out[M,1000] = X[M,1000] @ W[1000,1000]^T + bias (fp32 acc)
//   CTA tile 128x128 (8 warps, warp tile 32x64), BK=64 bf16 (16 K-tiles,
//   K zero-padded to 1024), 2-stage cp.async, 2 CTAs/SM, ldmatrix fragments.
//   smem row stride 88 bf16 (176B): 16B-aligned cp.async, conflict-free LDSM.
// ---------------------------------------------------------------------------
#define GROWB   176
#define GA_BYTES (128 * GROWB)            // 22528
#define GSTAGE_BYTES (2 * GA_BYTES)       // 45056 (A + B)
#define GSMEM_BYTES (2 * GSTAGE_BYTES)    // 90112 (2 stages)
#define GKTILES 16

__global__ __launch_bounds__(256, 2)
void gemm_bf16_kernel(const __nv_bfloat16* __restrict__ X,
                      const __nv_bfloat16* __restrict__ W,
                      const float* __restrict__ bias,
                      float* __restrict__ out)
{
    extern __shared__ __align__(16) char sm[];
    const uint32_t smu = (uint32_t)__cvta_generic_to_shared(sm);

    const int t      = threadIdx.x;
    const int warp   = t >> 5;
    const int lane   = t & 31;
    const int warp_m = warp >> 1;    // 0..3  (32 rows each)
    const int warp_n = warp & 1;     // 0..1  (64 cols each)
    const int g      = lane >> 2;    // 0..7
    const int tig    = lane & 3;     // 0..3
    const int m0     = blockIdx.y * 128;
    const int n0     = blockIdx.x * 128;

    // ldmatrix lane-address components (within tile, bytes)
    // A (per mi,kk): row = warp_m*32 + mi*16 + (lane&15), khalf = lane>>4
    const uint32_t aOff = (uint32_t)((warp_m * 32 + (lane & 15)) * GROWB
                                     + (lane >> 4) * 16);
    // B (per nip,kk): row = warp_n*64 + nip*16 + (lane>>4)*8 + (lane&7),
    //                 khalf = (lane>>3)&1
    const uint32_t bOff = (uint32_t)((warp_n * 64 + (lane >> 4) * 8 + (lane & 7)) * GROWB
                                     + ((lane >> 3) & 1) * 16);

    float acc[2][8][4];
    #pragma unroll
    for (int mi = 0; mi < 2; mi++)
        #pragma unroll
        for (int ni = 0; ni < 8; ni++)
            #pragma unroll
            for (int c = 0; c < 4; c++) acc[mi][ni][c] = 0.f;

    auto stage = [&](int s) {
        char* base = sm + (s & 1) * GSTAGE_BYTES;
        char* dA = base;
        char* dB = base + GA_BYTES;
        const int k0 = s * 64;
        #pragma unroll
        for (int i = 0; i < 4; i++) {             // A: 128 rows x 8 chunks(8 bf16)
            int u = t + i * 256;
            int row = u >> 3, ch = u & 7;
            bool v = (k0 + ch * 8) < Hn;          // 1000 % 8 == 0: no straddle
            cp16(dA + row * GROWB + ch * 16,
                 X + (size_t)(m0 + row) * Hn + k0 + ch * 8, v);
        }
        #pragma unroll
        for (int i = 0; i < 4; i++) {             // B: 128 rows x 8 chunks
            int u = t + i * 256;
            int row = u >> 3, ch = u & 7;
            bool v = ((k0 + ch * 8) < Hn) && ((n0 + row) < Hn);
            cp16(dB + row * GROWB + ch * 16,
                 W + (size_t)(n0 + row) * Hn + k0 + ch * 8, v);
        }
        asm volatile("cp.async.commit_group;\n");
    };

    stage(0);
    stage(1);

    for (int s = 0; s < GKTILES; s++) {
        if (s < GKTILES - 1) asm volatile("cp.async.wait_group 1;\n");
        else                 asm volatile("cp.async.wait_group 0;\n");
        __syncthreads();

        const uint32_t smA = smu + (s & 1) * GSTAGE_BYTES;
        const uint32_t smB = smA + GA_BYTES;

        #pragma unroll
        for (int kk = 0; kk < 4; kk++) {
            const uint32_t kb = kk * 32;          // byte offset of k16 group
            uint32_t a[2][4];
            ldsm_x4(a[0][0], a[0][1], a[0][2], a[0][3], smA + aOff + kb);
            ldsm_x4(a[1][0], a[1][1], a[1][2], a[1][3],
                    smA + aOff + 16 * GROWB + kb);
            uint32_t b0[8], b1[8];
            #pragma unroll
            for (int nip = 0; nip < 4; nip++) {
                ldsm_x4(b0[2 * nip], b1[2 * nip], b0[2 * nip + 1], b1[2 * nip + 1],
                        smB + bOff + nip * (16 * GROWB) + kb);
            }
            #pragma unroll
            for (int mi = 0; mi < 2; mi++)
                #pragma unroll
                for (int ni = 0; ni < 8; ni++)
                    mma_bf16(acc[mi][ni], a[mi], b0[ni], b1[ni]);
        }

        if (s + 2 < GKTILES) {
            __syncthreads();           // all warps done reading buffer s&1
            stage(s + 2);
        }
    }

    // epilogue: +bias, guarded float2 stores
    #pragma unroll
    for (int mi = 0; mi < 2; mi++) {
        const int row = m0 + warp_m * 32 + mi * 16 + g;
        #pragma unroll
        for (int ni = 0; ni < 8; ni++) {
            const int col = n0 + warp_n * 64 + ni * 8 + tig * 2;
            if (col < Hn) {
                float2 bb = *(const float2*)(bias + col);
                float2 r0 = make_float2(acc[mi][ni][0] + bb.x,
                                        acc[mi][ni][1] + bb.y);
                float2 r1 = make_float2(acc[mi][ni][2] + bb.x,
                                        acc[mi][ni][3] + bb.y);
                *(float2*)(out + (size_t)row * Hn + col)       = r0;
                *(float2*)(out + (size_t)(row + 8) * Hn + col) = r1;
            }
        }
    }
}

// ---------------------------------------------------------------------------
// Flash attention: block = (64 q rows, head, batch), 512 threads.
// fp32 SIMT with f32x2 FMA; register softmax + 8-lane shfl reductions.
// Output written as bf16 (feeds Wo GEMM directly).
// ---------------------------------------------------------------------------
#define AQS  132
#define ATTN_SMEM_FLOATS (64*AQS + 32*AQS + 32*AQS + 64*33 + 32)
#define ATTN_SMEM_BYTES  (ATTN_SMEM_FLOATS * 4)

__global__ __launch_bounds__(512)
void attn_kernel(const int* __restrict__ mask)
{
    extern __shared__ __align__(16) char smraw[];
    float* Qs  = (float*)smraw;               // [64][132]
    float* Ks  = Qs + 64 * AQS;               // [32][132]
    float* Vs  = Ks + 32 * AQS;               // [32][132]
    float* Ps  = Vs + 32 * AQS;               // [64][33]
    int*   msk = (int*)(Ps + 64 * 33);        // [32]

    const int t    = threadIdx.x;
    const int q0   = blockIdx.x * 64;
    const int h    = blockIdx.y;
    const int b    = blockIdx.z;
    const int qrow = t >> 3;      // 0..63
    const int grp  = t & 7;       // 0..7

    for (int e = t; e < 64 * DKn; e += 512) {
        int qq = e / DKn, d = e % DKn;
        Qs[qq * AQS + d] = g_qh[(size_t)(b * Sn + q0 + qq) * Hn + h * DKn + d];
    }
    if (t < 448) { Qs[(t / 7) * AQS + 125 + t % 7] = 0.f; }
    if (t < 224) {
        int r = t / 7, d = 125 + t % 7;
        Ks[r * AQS + d] = 0.f;
        Vs[r * AQS + d] = 0.f;
    }

    float m_reg = -1e30f, l_reg = 0.f;
    unsigned long long z2[8];
    #pragma unroll
    for (int i = 0; i < 8; i++) z2[i] = 0ull;

    const float scale = 0.08944271909999159f;   // 1/sqrt(125)

    for (int kt = 0; kt < Sn; kt += 32) {
        __syncthreads();

        for (int e = t; e < 32 * DKn; e += 512) {
            int j = e / DKn, d = e % DKn;
            size_t base = (size_t)(b * Sn + kt + j) * Hn + h * DKn;
            Ks[j * AQS + d] = g_kh[base + d];
            Vs[j * AQS + d] = g_vh[base + d];
        }
        if (t < 32) msk[t] = mask[b * Sn + kt + t];
        __syncthreads();

        // scores for keys j = grp + 8*jj
        unsigned long long acc2[4] = {0ull, 0ull, 0ull, 0ull};
        const float* qrowp = Qs + qrow * AQS;
        #pragma unroll 3
        for (int d = 0; d < AQS; d += 4) {
            ulonglong2 qq = *(const ulonglong2*)(qrowp + d);
            #pragma unroll
            for (int jj = 0; jj < 4; jj++) {
                ulonglong2 kk = *(const ulonglong2*)(Ks + (grp + 8 * jj) * AQS + d);
                fma2(acc2[jj], qq.x, kk.x);
                fma2(acc2[jj], qq.y, kk.y);
            }
        }
        float s[4];
        #pragma unroll
        for (int jj = 0; jj < 4; jj++) {
            float lo, hi;
            upk2(acc2[jj], lo, hi);
            s[jj] = (lo + hi) * scale;
            if (msk[grp + 8 * jj] != 0) s[jj] = -10000.f;
        }

        // online softmax (registers + 8-lane shfl)
        float tmax = fmaxf(fmaxf(s[0], s[1]), fmaxf(s[2], s[3]));
        tmax = fmaxf(tmax, __shfl_xor_sync(0xFFFFFFFFu, tmax, 1));
        tmax = fmaxf(tmax, __shfl_xor_sync(0xFFFFFFFFu, tmax, 2));
        tmax = fmaxf(tmax, __shfl_xor_sync(0xFFFFFFFFu, tmax, 4));
        float nm   = fmaxf(m_reg, tmax);
        float corr = __expf(m_reg - nm);
        float e0 = __expf(s[0] - nm), e1 = __expf(s[1] - nm);
        float e2 = __expf(s[2] - nm), e3 = __expf(s[3] - nm);
        float ps = e0 + e1 + e2 + e3;
        ps += __shfl_xor_sync(0xFFFFFFFFu, ps, 1);
        ps += __shfl_xor_sync(0xFFFFFFFFu, ps, 2);
        ps += __shfl_xor_sync(0xFFFFFFFFu, ps, 4);
        l_reg = l_reg * corr + ps;
        m_reg = nm;
        Ps[qrow * 33 + grp     ] = e0;
        Ps[qrow * 33 + grp + 8 ] = e1;
        Ps[qrow * 33 + grp + 16] = e2;
        Ps[qrow * 33 + grp + 24] = e3;
        __syncwarp();

        // z += P @ V
        {
            unsigned long long c2 = pk2(corr, corr);
            #pragma unroll
            for (int i = 0; i < 8; i++) mul2(z2[i], c2);
            const float* prow = Ps + qrow * 33;
            #pragma unroll 4
            for (int j = 0; j < 32; j++) {
                float p = prow[j];
                unsigned long long p2 = pk2(p, p);
                const float* vr = Vs + j * AQS + grp * 4;
                #pragma unroll
                for (int i = 0; i < 4; i++) {
                    ulonglong2 vv = *(const ulonglong2*)(vr + 32 * i);
                    fma2(z2[2 * i],     p2, vv.x);
                    fma2(z2[2 * i + 1], p2, vv.y);
                }
            }
        }
    }

    // normalized output -> bf16 (consumed by Wo GEMM)
    float inv = 1.f / l_reg;
    size_t ob = (size_t)(b * Sn + q0 + qrow) * Hn + h * DKn;
    #pragma unroll
    for (int i = 0; i < 4; i++) {
        int d = grp * 4 + 32 * i;
        float f0, f1, f2, f3;
        upk2(z2[2 * i], f0, f1);
        upk2(z2[2 * i + 1], f2, f3);
        float r[4] = {f0 * inv, f1 * inv, f2 * inv, f3 * inv};
        #pragma unroll
        for (int c = 0; c < 4; c++) {
            if (d + c < DKn)
                g_zb[ob + d + c] = __float2bfloat16_rn(r[c]);
        }
    }
}

// ---------------------------------------------------------------------------
// Residual + LayerNorm: out = LN(x + y) * g + b, per row of 1000
// ---------------------------------------------------------------------------
__global__ __launch_bounds__(256)
void ln_kernel(const float* __restrict__ x, const float* __restrict__ y,
               const float* __restrict__ gamma, const float* __restrict__ beta,
               float* __restrict__ out)
{
    __shared__ float buf[Hn];
    __shared__ float red1[8], red2[8];
    __shared__ float mu_s, rs_s;

    const int r = blockIdx.x;
    const int t = threadIdx.x;
    const size_t base = (size_t)r * Hn;

    float s1 = 0.f, s2 = 0.f;
    for (int c = t; c < Hn; c += 256) {
        float vv = x[base + c] + y[base + c];
        buf[c] = vv;
        s1 += vv;
        s2 += vv * vv;
    }
    #pragma unroll
    for (int o = 16; o; o >>= 1) {
        s1 += __shfl_down_sync(0xFFFFFFFFu, s1, o);
        s2 += __shfl_down_sync(0xFFFFFFFFu, s2, o);
    }
    if ((t & 31) == 0) { red1[t >> 5] = s1; red2[t >> 5] = s2; }
    __syncthreads();
    if (t == 0) {
        float a = 0.f, bq = 0.f;
        #pragma unroll
        for (int i = 0; i < 8; i++) { a += red1[i]; bq += red2[i]; }
        float mu  = a * (1.f / Hn);
        float var = bq * (1.f / Hn) - mu * mu;
        mu_s = mu;
        rs_s = rsqrtf(fmaxf(var, 0.f) + 1e-5f);
    }
    __syncthreads();
    float mu = mu_s, rs = rs_s;
    for (int c = t; c < Hn; c += 256)
        out[base + c] = (buf[c] - mu) * rs * gamma[c] + beta[c];
}

// ---------------------------------------------------------------------------
// Host entry  (launch order puts gemm_bf16 at capture slot 5 for ncu)
// ---------------------------------------------------------------------------
extern "C" void kernel_launch(void* const* d_in, const int* in_sizes, int n_in,
                              void* d_out, int out_size)
{
    const float* q    = (const float*)d_in[0];
    const float* k    = (const float*)d_in[1];
    const float* v    = (const float*)d_in[2];
    const int*   mask = (const int*)d_in[3];
    const float* Wq_w = (const float*)d_in[4];
    const float* Wq_b = (const float*)d_in[5];
    const float* Wk_w = (const float*)d_in[6];
    const float* Wk_b = (const float*)d_in[7];
    const float* Wv_w = (const float*)d_in[8];
    const float* Wv_b = (const float*)d_in[9];
    const float* Wo_w = (const float*)d_in[10];
    const float* Wo_b = (const float*)d_in[11];
    const float* ln_g = (const float*)d_in[12];
    const float* ln_b = (const float*)d_in[13];
    float* out = (float*)d_out;

    float *qh, *kh, *vh, *y;
    __nv_bfloat16 *qb, *kb, *vb, *zb, *wqb, *wkb, *wvb, *wob;
    cudaGetSymbolAddress((void**)&qh,  g_qh);
    cudaGetSymbolAddress((void**)&kh,  g_kh);
    cudaGetSymbolAddress((void**)&vh,  g_vh);
    cudaGetSymbolAddress((void**)&y,   g_y);
    cudaGetSymbolAddress((void**)&qb,  g_qb);
    cudaGetSymbolAddress((void**)&kb,  g_kb);
    cudaGetSymbolAddress((void**)&vb,  g_vb);
    cudaGetSymbolAddress((void**)&zb,  g_zb);
    cudaGetSymbolAddress((void**)&wqb, g_wqb);
    cudaGetSymbolAddress((void**)&wkb, g_wkb);
    cudaGetSymbolAddress((void**)&wvb, g_wvb);
    cudaGetSymbolAddress((void**)&wob, g_wob);

    const int n8_big = (Mrows * Hn) / 8;
    const int n8_w   = (Hn * Hn) / 8;
    const int gb_big = (n8_big + 255) / 256;
    const int gb_w   = (n8_w + 255) / 256;

    cudaFuncSetAttribute(gemm_bf16_kernel,
                         cudaFuncAttributeMaxDynamicSharedMemorySize,
                         GSMEM_BYTES);
    dim3 gg(8, Mrows / 128);   // 8 N-tiles x 512 M-tiles

    // launches 0..4
    conv_bf16_kernel<<<gb_big, 256>>>(q, qb, n8_big);
    conv_bf16_kernel<<<gb_big, 256>>>(k, kb, n8_big);
    conv_bf16_kernel<<<gb_big, 256>>>(v, vb, n8_big);
    conv_bf16_kernel<<<gb_w, 256>>>(Wq_w, wqb, n8_w);
    conv_bf16_kernel<<<gb_w, 256>>>(Wk_w, wkb, n8_w);
    // launch 5 = GEMM (ncu -s 5 -c 1 captures this)
    gemm_bf16_kernel<<<gg, 256, GSMEM_BYTES>>>(qb, wqb, Wq_b, qh);
    // remaining convs + gemms
    conv_bf16_kernel<<<gb_w, 256>>>(Wv_w, wvb, n8_w);
    conv_bf16_kernel<<<gb_w, 256>>>(Wo_w, wob, n8_w);
    gemm_bf16_kernel<<<gg, 256, GSMEM_BYTES>>>(kb, wkb, Wk_b, kh);
    gemm_bf16_kernel<<<gg, 256, GSMEM_BYTES>>>(vb, wvb, Wv_b, vh);

    cudaFuncSetAttribute(attn_kernel,
                         cudaFuncAttributeMaxDynamicSharedMemorySize,
                         ATTN_SMEM_BYTES);
    attn_kernel<<<dim3(Sn / 64, NHn, Bn), 512, ATTN_SMEM_BYTES>>>(mask);

    gemm_bf16_kernel<<<gg, 256, GSMEM_BYTES>>>(zb, wob, Wo_b, y);

    ln_kernel<<<Mrows, 256>>>(q, y, ln_g, ln_b, out);
}

// round 8
// speedup vs baseline: 10.1887x; 3.5134x over previous
#include <cuda_runtime.h>
#include <cuda_bf16.h>
#include <cuda_fp16.h>
#include <cstdint>

// Problem constants
#define Bn   128
#define Sn   512
#define Hn   1000
#define NHn  8
#define DKn  125
#define Mrows (Bn * Sn)        // 65536

// ---------------------------------------------------------------------------
// Scratch (device globals; allocation in kernel_launch is forbidden)
// ---------------------------------------------------------------------------
__device__ __align__(16) float g_y [(size_t)Mrows * Hn];
__device__ __align__(16) __nv_bfloat16 g_qb[(size_t)Mrows * Hn];
__device__ __align__(16) __nv_bfloat16 g_kb[(size_t)Mrows * Hn];
__device__ __align__(16) __nv_bfloat16 g_vb[(size_t)Mrows * Hn];
__device__ __align__(16) __nv_bfloat16 g_zb[(size_t)Mrows * Hn];
__device__ __align__(16) __nv_bfloat16 g_wqb[(size_t)Hn * Hn];
__device__ __align__(16) __nv_bfloat16 g_wkb[(size_t)Hn * Hn];
__device__ __align__(16) __nv_bfloat16 g_wvb[(size_t)Hn * Hn];
__device__ __align__(16) __nv_bfloat16 g_wob[(size_t)Hn * Hn];
// head-padded fp16 projections: [Mrows][8 heads][128] (dims 125..127 zero)
__device__ __align__(16) __half g_qh16[(size_t)Mrows * 1024];
__device__ __align__(16) __half g_kh16[(size_t)Mrows * 1024];
__device__ __align__(16) __half g_vh16[(size_t)Mrows * 1024];

// ---------------------------------------------------------------------------
// helpers
// ---------------------------------------------------------------------------
__device__ __forceinline__ void mma_bf16(float* d, const uint32_t* a,
                                         uint32_t b0, uint32_t b1) {
    asm volatile(
        "mma.sync.aligned.m16n8k16.row.col.f32.bf16.bf16.f32 "
        "{%0,%1,%2,%3}, {%4,%5,%6,%7}, {%8,%9}, {%0,%1,%2,%3};"
        : "+f"(d[0]), "+f"(d[1]), "+f"(d[2]), "+f"(d[3])
        : "r"(a[0]), "r"(a[1]), "r"(a[2]), "r"(a[3]), "r"(b0), "r"(b1));
}
__device__ __forceinline__ void mma_f16(float* d, uint32_t a0, uint32_t a1,
                                        uint32_t a2, uint32_t a3,
                                        uint32_t b0, uint32_t b1) {
    asm volatile(
        "mma.sync.aligned.m16n8k16.row.col.f32.f16.f16.f32 "
        "{%0,%1,%2,%3}, {%4,%5,%6,%7}, {%8,%9}, {%0,%1,%2,%3};"
        : "+f"(d[0]), "+f"(d[1]), "+f"(d[2]), "+f"(d[3])
        : "r"(a0), "r"(a1), "r"(a2), "r"(a3), "r"(b0), "r"(b1));
}
__device__ __forceinline__ void ldsm_x4(uint32_t &r0, uint32_t &r1,
                                        uint32_t &r2, uint32_t &r3,
                                        uint32_t addr) {
    asm volatile("ldmatrix.sync.aligned.m8n8.x4.shared.b16 {%0,%1,%2,%3}, [%4];"
                 : "=r"(r0), "=r"(r1), "=r"(r2), "=r"(r3) : "r"(addr));
}
__device__ __forceinline__ void ldsm_x4_t(uint32_t &r0, uint32_t &r1,
                                          uint32_t &r2, uint32_t &r3,
                                          uint32_t addr) {
    asm volatile("ldmatrix.sync.aligned.m8n8.x4.trans.shared.b16 {%0,%1,%2,%3}, [%4];"
                 : "=r"(r0), "=r"(r1), "=r"(r2), "=r"(r3) : "r"(addr));
}
__device__ __forceinline__ void cp16(void* smem_dst, const void* gsrc, bool valid) {
    uint32_t sa = (uint32_t)__cvta_generic_to_shared(smem_dst);
    int sz = valid ? 16 : 0;
    asm volatile("cp.async.ca.shared.global [%0], [%1], 16, %2;\n"
                 :: "r"(sa), "l"(gsrc), "r"(sz));
}
__device__ __forceinline__ uint32_t h2pack(float x, float y) {
    __half2 h = __floats2half2_rn(x, y);
    return *(uint32_t*)&h;
}

// ---------------------------------------------------------------------------
// f32 -> bf16 conversion (rn), 8 elements per thread
// ---------------------------------------------------------------------------
__global__ __launch_bounds__(256)
void conv_bf16_kernel(const float* __restrict__ in,
                      __nv_bfloat16* __restrict__ out, int n8)
{
    int i = blockIdx.x * 256 + threadIdx.x;
    if (i >= n8) return;
    float4 v0 = ((const float4*)in)[2 * i];
    float4 v1 = ((const float4*)in)[2 * i + 1];
    __nv_bfloat162 p0 = __floats2bfloat162_rn(v0.x, v0.y);
    __nv_bfloat162 p1 = __floats2bfloat162_rn(v0.z, v0.w);
    __nv_bfloat162 p2 = __floats2bfloat162_rn(v1.x, v1.y);
    __nv_bfloat162 p3 = __floats2bfloat162_rn(v1.z, v1.w);
    uint4 u;
    u.x = *(uint32_t*)&p0; u.y = *(uint32_t*)&p1;
    u.z = *(uint32_t*)&p2; u.w = *(uint32_t*)&p3;
    ((uint4*)out)[i] = u;
}

// All 4 weight matrices in one launch (keeps GEMMs at early ncu slots)
__global__ __launch_bounds__(256)
void conv_w4_kernel(const float* __restrict__ w0, const float* __restrict__ w1,
                    const float* __restrict__ w2, const float* __restrict__ w3,
                    int n8)
{
    int i = blockIdx.x * 256 + threadIdx.x;
    if (i >= n8) return;
    const float* src = (blockIdx.y == 0) ? w0 : (blockIdx.y == 1) ? w1
                     : (blockIdx.y == 2) ? w2 : w3;
    __nv_bfloat16* dst = (blockIdx.y == 0) ? g_wqb : (blockIdx.y == 1) ? g_wkb
                       : (blockIdx.y == 2) ? g_wvb : g_wob;
    float4 v0 = ((const float4*)src)[2 * i];
    float4 v1 = ((const float4*)src)[2 * i + 1];
    __nv_bfloat162 p0 = __floats2bfloat162_rn(v0.x, v0.y);
    __nv_bfloat162 p1 = __floats2bfloat162_rn(v0.z, v0.w);
    __nv_bfloat162 p2 = __floats2bfloat162_rn(v1.x, v1.y);
    __nv_bfloat162 p3 = __floats2bfloat162_rn(v1.z, v1.w);
    uint4 u;
    u.x = *(uint32_t*)&p0; u.y = *(uint32_t*)&p1;
    u.z = *(uint32_t*)&p2; u.w = *(uint32_t*)&p3;
    ((uint4*)dst)[i] = u;
}

// Zero the per-head pad dims (125..127) of the fp16 projection buffers
__global__ __launch_bounds__(256)
void pad_kernel()
{
    int idx = blockIdx.x * 256 + threadIdx.x;
    if (idx >= Mrows * 8) return;
    int row = idx >> 3, h = idx & 7;
    size_t off = (size_t)row * 1024 + h * 128 + 125;
    __half z = __float2half(0.f);
    g_qh16[off] = z; g_qh16[off + 1] = z; g_qh16[off + 2] = z;
    g_kh16[off] = z; g_kh16[off + 1] = z; g_kh16[off + 2] = z;
    g_vh16[off] = z; g_vh16[off + 1] = z; g_vh16[off + 2] = z;
}

// ---------------------------------------------------------------------------
// BF16 mma.sync GEMM: D[M,1000] = X @ W^T + bias  (fp32 acc)
//   mode 0: write f32 to out[row*1000 + col]
//   mode 1: write fp16*(scale) to head-padded layout [row*1024 + h*128 + d]
// ---------------------------------------------------------------------------
#define GROWB   176
#define GA_BYTES (128 * GROWB)
#define GSTAGE_BYTES (2 * GA_BYTES)
#define GSMEM_BYTES (2 * GSTAGE_BYTES)    // 90112
#define GKTILES 16

__global__ __launch_bounds__(256, 2)
void gemm_bf16_kernel(const __nv_bfloat16* __restrict__ X,
                      const __nv_bfloat16* __restrict__ W,
                      const float* __restrict__ bias,
                      void* __restrict__ outv, int mode, float scale)
{
    extern __shared__ __align__(16) char sm[];
    const uint32_t smu = (uint32_t)__cvta_generic_to_shared(sm);

    const int t      = threadIdx.x;
    const int warp   = t >> 5;
    const int lane   = t & 31;
    const int warp_m = warp >> 1;
    const int warp_n = warp & 1;
    const int g      = lane >> 2;
    const int tig    = lane & 3;
    const int m0     = blockIdx.y * 128;
    const int n0     = blockIdx.x * 128;

    const uint32_t aOff = (uint32_t)((warp_m * 32 + (lane & 15)) * GROWB
                                     + (lane >> 4) * 16);
    const uint32_t bOff = (uint32_t)((warp_n * 64 + (lane >> 4) * 8 + (lane & 7)) * GROWB
                                     + ((lane >> 3) & 1) * 16);

    float acc[2][8][4];
    #pragma unroll
    for (int mi = 0; mi < 2; mi++)
        #pragma unroll
        for (int ni = 0; ni < 8; ni++)
            #pragma unroll
            for (int c = 0; c < 4; c++) acc[mi][ni][c] = 0.f;

    auto stage = [&](int s) {
        char* base = sm + (s & 1) * GSTAGE_BYTES;
        char* dA = base;
        char* dB = base + GA_BYTES;
        const int k0 = s * 64;
        #pragma unroll
        for (int i = 0; i < 4; i++) {
            int u = t + i * 256;
            int row = u >> 3, ch = u & 7;
            bool v = (k0 + ch * 8) < Hn;
            cp16(dA + row * GROWB + ch * 16,
                 X + (size_t)(m0 + row) * Hn + k0 + ch * 8, v);
        }
        #pragma unroll
        for (int i = 0; i < 4; i++) {
            int u = t + i * 256;
            int row = u >> 3, ch = u & 7;
            bool v = ((k0 + ch * 8) < Hn) && ((n0 + row) < Hn);
            cp16(dB + row * GROWB + ch * 16,
                 W + (size_t)(n0 + row) * Hn + k0 + ch * 8, v);
        }
        asm volatile("cp.async.commit_group;\n");
    };

    stage(0);
    stage(1);

    for (int s = 0; s < GKTILES; s++) {
        if (s < GKTILES - 1) asm volatile("cp.async.wait_group 1;\n");
        else                 asm volatile("cp.async.wait_group 0;\n");
        __syncthreads();

        const uint32_t smA = smu + (s & 1) * GSTAGE_BYTES;
        const uint32_t smB = smA + GA_BYTES;

        #pragma unroll
        for (int kk = 0; kk < 4; kk++) {
            const uint32_t kb = kk * 32;
            uint32_t a[2][4];
            ldsm_x4(a[0][0], a[0][1], a[0][2], a[0][3], smA + aOff + kb);
            ldsm_x4(a[1][0], a[1][1], a[1][2], a[1][3],
                    smA + aOff + 16 * GROWB + kb);
            uint32_t b0[8], b1[8];
            #pragma unroll
            for (int nip = 0; nip < 4; nip++) {
                ldsm_x4(b0[2 * nip], b1[2 * nip], b0[2 * nip + 1], b1[2 * nip + 1],
                        smB + bOff + nip * (16 * GROWB) + kb);
            }
            #pragma unroll
            for (int mi = 0; mi < 2; mi++)
                #pragma unroll
                for (int ni = 0; ni < 8; ni++)
                    mma_bf16(acc[mi][ni], a[mi], b0[ni], b1[ni]);
        }

        if (s + 2 < GKTILES) {
            __syncthreads();
            stage(s + 2);
        }
    }

    if (mode == 0) {
        float* out = (float*)outv;
        #pragma unroll
        for (int mi = 0; mi < 2; mi++) {
            const int row = m0 + warp_m * 32 + mi * 16 + g;
            #pragma unroll
            for (int ni = 0; ni < 8; ni++) {
                const int col = n0 + warp_n * 64 + ni * 8 + tig * 2;
                if (col < Hn) {
                    float2 bb = *(const float2*)(bias + col);
                    float2 r0 = make_float2(acc[mi][ni][0] + bb.x,
                                            acc[mi][ni][1] + bb.y);
                    float2 r1 = make_float2(acc[mi][ni][2] + bb.x,
                                            acc[mi][ni][3] + bb.y);
                    *(float2*)(out + (size_t)row * Hn + col)       = r0;
                    *(float2*)(out + (size_t)(row + 8) * Hn + col) = r1;
                }
            }
        }
    } else {
        __half* out = (__half*)outv;
        #pragma unroll
        for (int mi = 0; mi < 2; mi++) {
            const int row = m0 + warp_m * 32 + mi * 16 + g;
            #pragma unroll
            for (int ni = 0; ni < 8; ni++) {
                const int col = n0 + warp_n * 64 + ni * 8 + tig * 2;
                if (col < Hn) {
                    #pragma unroll
                    for (int e = 0; e < 2; e++) {
                        int c = col + e;
                        int hh = c / 125;
                        size_t doff = hh * 128 + (c - hh * 125);
                        float v0 = (acc[mi][ni][e]     + bias[c]) * scale;
                        float v1 = (acc[mi][ni][2 + e] + bias[c]) * scale;
                        out[(size_t)row * 1024 + doff]       = __float2half(v0);
                        out[(size_t)(row + 8) * 1024 + doff] = __float2half(v1);
                    }
                }
            }
        }
    }
}

// ---------------------------------------------------------------------------
// Tensor-core flash attention (fp16 mma, fp32 softmax/acc).
// CTA = 128 q-rows x (head, batch); 8 warps x 16 q-rows; key tiles of 64,
// double-buffered cp.async. P stays in registers (S-frag -> A-frag repack).
// Q pre-scaled by 1/sqrt(125) in the Q-projection epilogue.
// ---------------------------------------------------------------------------
#define ASK  272                       // bytes per 128-dim fp16 row (136 halves)
#define A_OQ 0
#define A_OK 34816                     // Q: 128*272
#define A_OV (A_OK + 2*17408)          // K bufs: 2 * 64*272
#define A_OM (A_OV + 2*17408)          // V bufs
#define A_SMEM (A_OM + 2*256 + 128)    // + mask bufs

__global__ __launch_bounds__(256, 1)
void attn_tc_kernel(const int* __restrict__ mask)
{
    extern __shared__ __align__(16) char sm[];
    const uint32_t smu = (uint32_t)__cvta_generic_to_shared(sm);

    const int t    = threadIdx.x;
    const int warp = t >> 5;
    const int lane = t & 31;
    const int tig  = lane & 3;
    const int q0   = blockIdx.x * 128;
    const int h    = blockIdx.y;
    const int b    = blockIdx.z;
    const size_t brow = (size_t)b * Sn;

    // stage Q (joins commit group of tile 0)
    #pragma unroll
    for (int i = 0; i < 8; i++) {
        int u = t + i * 256;
        int row = u >> 4, ch = u & 15;
        cp16(sm + A_OQ + row * ASK + ch * 16,
             g_qh16 + (brow + q0 + row) * 1024 + h * 128 + ch * 8, true);
    }

    auto stageKV = [&](int kt) {
        int bi = kt & 1;
        char* dK = sm + A_OK + bi * 17408;
        char* dV = sm + A_OV + bi * 17408;
        char* dM = sm + A_OM + bi * 256;
        #pragma unroll
        for (int i = 0; i < 4; i++) {
            int u = t + i * 256;
            int row = u >> 4, ch = u & 15;
            const size_t src = (brow + kt * 64 + row) * 1024 + h * 128 + ch * 8;
            cp16(dK + row * ASK + ch * 16, g_kh16 + src, true);
            cp16(dV + row * ASK + ch * 16, g_vh16 + src, true);
        }
        if (t < 16)
            cp16(dM + t * 16, mask + b * Sn + kt * 64 + t * 4, true);
        asm volatile("cp.async.commit_group;\n");
    };

    stageKV(0);
    stageKV(1);

    // ldmatrix lane-address bases
    const uint32_t aAddr = smu + A_OQ + (warp * 16 + (lane & 15)) * ASK
                           + (lane >> 4) * 16;                      // + kk*32
    const uint32_t kRow = (lane & 7) + ((lane & 16) ? 8 : 0);
    const uint32_t kCol = (lane & 8) ? 16 : 0;
    const uint32_t vRow = (lane & 7) + ((lane & 8) ? 8 : 0);
    const uint32_t vCol = (lane & 16) ? 16 : 0;

    float o[16][4];
    #pragma unroll
    for (int ni = 0; ni < 16; ni++)
        #pragma unroll
        for (int c = 0; c < 4; c++) o[ni][c] = 0.f;
    float m0r = -1e30f, m1r = -1e30f, l0r = 0.f, l1r = 0.f;

    for (int kt = 0; kt < 8; kt++) {
        if (kt < 7) asm volatile("cp.async.wait_group 1;\n");
        else        asm volatile("cp.async.wait_group 0;\n");
        __syncthreads();

        const uint32_t kBase = smu + A_OK + (kt & 1) * 17408 + kRow * ASK + kCol;
        const uint32_t vBase = smu + A_OV + (kt & 1) * 17408 + vRow * ASK + vCol;
        const int* mskp = (const int*)(sm + A_OM + (kt & 1) * 256);

        // ---- S = Q @ K^T (scaled Q) ----
        float s[8][4];
        #pragma unroll
        for (int j = 0; j < 8; j++)
            #pragma unroll
            for (int c = 0; c < 4; c++) s[j][c] = 0.f;

        #pragma unroll
        for (int kk = 0; kk < 8; kk++) {
            uint32_t a0, a1, a2, a3;
            ldsm_x4(a0, a1, a2, a3, aAddr + kk * 32);
            #pragma unroll
            for (int jj = 0; jj < 4; jj++) {
                uint32_t b0, b1, b2, b3;
                ldsm_x4(b0, b1, b2, b3, kBase + jj * (16 * ASK) + kk * 32);
                mma_f16(s[2 * jj],     a0, a1, a2, a3, b0, b1);
                mma_f16(s[2 * jj + 1], a0, a1, a2, a3, b2, b3);
            }
        }

        // ---- mask + online softmax (register resident) ----
        #pragma unroll
        for (int j = 0; j < 8; j++) {
            int c0 = 8 * j + 2 * tig;
            if (mskp[c0])     { s[j][0] = -10000.f; s[j][2] = -10000.f; }
            if (mskp[c0 + 1]) { s[j][1] = -10000.f; s[j][3] = -10000.f; }
        }
        float tm0 = -1e30f, tm1 = -1e30f;
        #pragma unroll
        for (int j = 0; j < 8; j++) {
            tm0 = fmaxf(tm0, fmaxf(s[j][0], s[j][1]));
            tm1 = fmaxf(tm1, fmaxf(s[j][2], s[j][3]));
        }
        tm0 = fmaxf(tm0, __shfl_xor_sync(0xFFFFFFFFu, tm0, 1));
        tm0 = fmaxf(tm0, __shfl_xor_sync(0xFFFFFFFFu, tm0, 2));
        tm1 = fmaxf(tm1, __shfl_xor_sync(0xFFFFFFFFu, tm1, 1));
        tm1 = fmaxf(tm1, __shfl_xor_sync(0xFFFFFFFFu, tm1, 2));
        float nm0 = fmaxf(m0r, tm0), nm1 = fmaxf(m1r, tm1);
        float cr0 = __expf(m0r - nm0), cr1 = __expf(m1r - nm1);
        float sum0 = 0.f, sum1 = 0.f;
        #pragma unroll
        for (int j = 0; j < 8; j++) {
            s[j][0] = __expf(s[j][0] - nm0);
            s[j][1] = __expf(s[j][1] - nm0);
            s[j][2] = __expf(s[j][2] - nm1);
            s[j][3] = __expf(s[j][3] - nm1);
            sum0 += s[j][0] + s[j][1];
            sum1 += s[j][2] + s[j][3];
        }
        sum0 += __shfl_xor_sync(0xFFFFFFFFu, sum0, 1);
        sum0 += __shfl_xor_sync(0xFFFFFFFFu, sum0, 2);
        sum1 += __shfl_xor_sync(0xFFFFFFFFu, sum1, 1);
        sum1 += __shfl_xor_sync(0xFFFFFFFFu, sum1, 2);
        l0r = l0r * cr0 + sum0;  m0r = nm0;
        l1r = l1r * cr1 + sum1;  m1r = nm1;
        #pragma unroll
        for (int ni = 0; ni < 16; ni++) {
            o[ni][0] *= cr0; o[ni][1] *= cr0;
            o[ni][2] *= cr1; o[ni][3] *= cr1;
        }

        // ---- O += P @ V  (P repacked from S frags, V via ldmatrix.trans) ----
        #pragma unroll
        for (int kk = 0; kk < 4; kk++) {
            uint32_t a0 = h2pack(s[2 * kk][0],     s[2 * kk][1]);
            uint32_t a1 = h2pack(s[2 * kk][2],     s[2 * kk][3]);
            uint32_t a2 = h2pack(s[2 * kk + 1][0], s[2 * kk + 1][1]);
            uint32_t a3 = h2pack(s[2 * kk + 1][2], s[2 * kk + 1][3]);
            #pragma unroll
            for (int nn = 0; nn < 8; nn++) {
                uint32_t b0, b1, b2, b3;
                ldsm_x4_t(b0, b1, b2, b3, vBase + kk * (16 * ASK) + nn * 32);
                mma_f16(o[2 * nn],     a0, a1, a2, a3, b0, b1);
                mma_f16(o[2 * nn + 1], a0, a1, a2, a3, b2, b3);
            }
        }

        if (kt + 2 < 8) {
            __syncthreads();
            stageKV(kt + 2);
        }
    }

    // ---- normalize + write z as bf16 into [Mrows][1000] layout ----
    float inv0 = 1.f / l0r, inv1 = 1.f / l1r;
    const int g = lane >> 2;
    const int row0 = b * Sn + q0 + warp * 16 + g;
    const size_t base0 = (size_t)row0 * Hn + h * DKn;
    const size_t base1 = base0 + (size_t)8 * Hn;
    #pragma unroll
    for (int ni = 0; ni < 16; ni++) {
        int d = ni * 8 + 2 * tig;
        if (d < DKn) {
            g_zb[base0 + d] = __float2bfloat16_rn(o[ni][0] * inv0);
            g_zb[base1 + d] = __float2bfloat16_rn(o[ni][2] * inv1);
        }
        if (d + 1 < DKn) {
            g_zb[base0 + d + 1] = __float2bfloat16_rn(o[ni][1] * inv0);
            g_zb[base1 + d + 1] = __float2bfloat16_rn(o[ni][3] * inv1);
        }
    }
}

// ---------------------------------------------------------------------------
// Residual + LayerNorm: out = LN(x + y) * g + b, per row of 1000
// ---------------------------------------------------------------------------
__global__ __launch_bounds__(256)
void ln_kernel(const float* __restrict__ x, const float* __restrict__ y,
               const float* __restrict__ gamma, const float* __restrict__ beta,
               float* __restrict__ out)
{
    __shared__ float buf[Hn];
    __shared__ float red1[8], red2[8];
    __shared__ float mu_s, rs_s;

    const int r = blockIdx.x;
    const int t = threadIdx.x;
    const size_t base = (size_t)r * Hn;

    float s1 = 0.f, s2 = 0.f;
    for (int c = t; c < Hn; c += 256) {
        float vv = x[base + c] + y[base + c];
        buf[c] = vv;
        s1 += vv;
        s2 += vv * vv;
    }
    #pragma unroll
    for (int o = 16; o; o >>= 1) {
        s1 += __shfl_down_sync(0xFFFFFFFFu, s1, o);
        s2 += __shfl_down_sync(0xFFFFFFFFu, s2, o);
    }
    if ((t & 31) == 0) { red1[t >> 5] = s1; red2[t >> 5] = s2; }
    __syncthreads();
    if (t == 0) {
        float a = 0.f, bq = 0.f;
        #pragma unroll
        for (int i = 0; i < 8; i++) { a += red1[i]; bq += red2[i]; }
        float mu  = a * (1.f / Hn);
        float var = bq * (1.f / Hn) - mu * mu;
        mu_s = mu;
        rs_s = rsqrtf(fmaxf(var, 0.f) + 1e-5f);
    }
    __syncthreads();
    float mu = mu_s, rs = rs_s;
    for (int c = t; c < Hn; c += 256)
        out[base + c] = (buf[c] - mu) * rs * gamma[c] + beta[c];
}

// ---------------------------------------------------------------------------
// Host entry
// ---------------------------------------------------------------------------
extern "C" void kernel_launch(void* const* d_in, const int* in_sizes, int n_in,
                              void* d_out, int out_size)
{
    const float* q    = (const float*)d_in[0];
    const float* k    = (const float*)d_in[1];
    const float* v    = (const float*)d_in[2];
    const int*   mask = (const int*)d_in[3];
    const float* Wq_w = (const float*)d_in[4];
    const float* Wq_b = (const float*)d_in[5];
    const float* Wk_w = (const float*)d_in[6];
    const float* Wk_b = (const float*)d_in[7];
    const float* Wv_w = (const float*)d_in[8];
    const float* Wv_b = (const float*)d_in[9];
    const float* Wo_w = (const float*)d_in[10];
    const float* Wo_b = (const float*)d_in[11];
    const float* ln_g = (const float*)d_in[12];
    const float* ln_b = (const float*)d_in[13];
    float* out = (float*)d_out;

    float* y;
    __nv_bfloat16 *qb, *kb, *vb, *zb, *wqb, *wkb, *wvb, *wob;
    __half *qh16, *kh16, *vh16;
    cudaGetSymbolAddress((void**)&y,    g_y);
    cudaGetSymbolAddress((void**)&qb,   g_qb);
    cudaGetSymbolAddress((void**)&kb,   g_kb);
    cudaGetSymbolAddress((void**)&vb,   g_vb);
    cudaGetSymbolAddress((void**)&zb,   g_zb);
    cudaGetSymbolAddress((void**)&wqb,  g_wqb);
    cudaGetSymbolAddress((void**)&wkb,  g_wkb);
    cudaGetSymbolAddress((void**)&wvb,  g_wvb);
    cudaGetSymbolAddress((void**)&wob,  g_wob);
    cudaGetSymbolAddress((void**)&qh16, g_qh16);
    cudaGetSymbolAddress((void**)&kh16, g_kh16);
    cudaGetSymbolAddress((void**)&vh16, g_vh16);

    const int n8_big = (Mrows * Hn) / 8;
    const int n8_w   = (Hn * Hn) / 8;
    const int gb_big = (n8_big + 255) / 256;
    const int gb_w   = (n8_w + 255) / 256;
    const float qscale = 0.08944271909999159f;   // 1/sqrt(125)

    cudaFuncSetAttribute(gemm_bf16_kernel,
                         cudaFuncAttributeMaxDynamicSharedMemorySize,
                         GSMEM_BYTES);
    cudaFuncSetAttribute(attn_tc_kernel,
                         cudaFuncAttributeMaxDynamicSharedMemorySize,
                         A_SMEM);
    dim3 gg(8, Mrows / 128);

    // 0,1: input convs; 2: all-weight conv; 3,4: GEMMs (ncu capture slots)
    conv_bf16_kernel<<<gb_big, 256>>>(q, qb, n8_big);
    conv_bf16_kernel<<<gb_big, 256>>>(k, kb, n8_big);
    conv_w4_kernel<<<dim3(gb_w, 4), 256>>>(Wq_w, Wk_w, Wv_w, Wo_w, n8_w);
    gemm_bf16_kernel<<<gg, 256, GSMEM_BYTES>>>(qb, wqb, Wq_b, qh16, 1, qscale);
    gemm_bf16_kernel<<<gg, 256, GSMEM_BYTES>>>(kb, wkb, Wk_b, kh16, 1, 1.f);
    conv_bf16_kernel<<<gb_big, 256>>>(v, vb, n8_big);
    gemm_bf16_kernel<<<gg, 256, GSMEM_BYTES>>>(vb, wvb, Wv_b, vh16, 1, 1.f);
    pad_kernel<<<(Mrows * 8 + 255) / 256, 256>>>();

    attn_tc_kernel<<<dim3(Sn / 128, NHn, Bn), 256, A_SMEM>>>(mask);

    gemm_bf16_kernel<<<gg, 256, GSMEM_BYTES>>>(zb, wob, Wo_b, y, 0, 1.f);

    ln_kernel<<<Mrows, 256>>>(q, y, ln_g, ln_b, out);
}